// round 14
// baseline (speedup 1.0000x reference)
#include <cuda_runtime.h>
#include <cuda_bf16.h>
#include <stdint.h>
#include <math.h>

// Problem constants
#define Bsz   4
#define Tsz   2048
#define DM    1024
#define Hn    16
#define HDsz  64
#define NFsz  128
#define CH    64
#define NCH   (Tsz / CH)      // 32
#define BHn   (Bsz * Hn)      // 64
#define EPSv  1e-6f
#define INV_SQRT_NF 0.08838834764831845f

#define M_ROWS (Bsz * Tsz)    // 8192
#define KP     (DM / 2)       // 512
#define FROWS  (BHn * Tsz)    // 131072

// -------------------- scratch (device globals) -----------------------------
__device__ float g_q [BHn * Tsz * HDsz];
__device__ float g_k [BHn * Tsz * HDsz];
__device__ float g_v [BHn * Tsz * HDsz];
__device__ float g_qp[BHn * Tsz * NFsz];
__device__ float g_kp[BHn * Tsz * NFsz];
__device__ float g_S [BHn * NCH * NFsz * HDsz];
__device__ float g_z [BHn * NCH * NFsz];
__device__ float g_y [Bsz * Tsz * Hn * HDsz];

__device__ unsigned g_Xh[KP * M_ROWS];
__device__ unsigned g_Xl[KP * M_ROWS];
__device__ unsigned g_Wh[4 * KP * DM];
__device__ unsigned g_Wl[4 * KP * DM];

// ---------------------------------------------------------------------------
// helpers
// ---------------------------------------------------------------------------
__device__ __forceinline__ void bsplit2(float v0, float v1, unsigned& hi, unsigned& lo) {
    __nv_bfloat16 h0 = __float2bfloat16_rn(v0);
    __nv_bfloat16 h1 = __float2bfloat16_rn(v1);
    float r0 = v0 - __bfloat162float(h0);
    float r1 = v1 - __bfloat162float(h1);
    __nv_bfloat16 l0 = __float2bfloat16_rn(r0);
    __nv_bfloat16 l1 = __float2bfloat16_rn(r1);
    hi = ((unsigned)__bfloat16_as_ushort(h1) << 16) | __bfloat16_as_ushort(h0);
    lo = ((unsigned)__bfloat16_as_ushort(l1) << 16) | __bfloat16_as_ushort(l0);
}

__device__ __forceinline__ float bf_lo(unsigned u) {
    return __bfloat162float(__ushort_as_bfloat16((unsigned short)(u & 0xffffu)));
}
__device__ __forceinline__ float bf_hi(unsigned u) {
    return __bfloat162float(__ushort_as_bfloat16((unsigned short)(u >> 16)));
}

__device__ __forceinline__ void mma_bf16(float c[4], const unsigned a[4], const unsigned b[2]) {
    asm volatile(
        "mma.sync.aligned.m16n8k16.row.col.f32.bf16.bf16.f32 "
        "{%0,%1,%2,%3}, {%4,%5,%6,%7}, {%8,%9}, {%0,%1,%2,%3};"
        : "+f"(c[0]), "+f"(c[1]), "+f"(c[2]), "+f"(c[3])
        : "r"(a[0]), "r"(a[1]), "r"(a[2]), "r"(a[3]), "r"(b[0]), "r"(b[1]));
}

#define CP16(dst, src) \
    asm volatile("cp.async.cg.shared.global [%0], [%1], 16;" :: "r"(dst), "l"(src))
#define CP_COMMIT() asm volatile("cp.async.commit_group;")
#define CP_WAIT1()  asm volatile("cp.async.wait_group 1;")

// ---------------------------------------------------------------------------
// pack_w (all 4 weights in one launch) / pack_x
// ---------------------------------------------------------------------------
__global__ __launch_bounds__(256) void pack_w4_kernel(
    const float* __restrict__ W0, const float* __restrict__ W1,
    const float* __restrict__ W2, const float* __restrict__ W3,
    unsigned* __restrict__ Wh, unsigned* __restrict__ Wl)
{
    const int w = blockIdx.y;
    const float* W = (w == 0) ? W0 : (w == 1) ? W1 : (w == 2) ? W2 : W3;
    const int idx = blockIdx.x * 256 + threadIdx.x;
    const int kp = idx >> 10, n = idx & 1023;
    const float v0 = W[(size_t)(2 * kp) * DM + n];
    const float v1 = W[(size_t)(2 * kp + 1) * DM + n];
    unsigned hi, lo;
    bsplit2(v0, v1, hi, lo);
    const size_t o = (size_t)w * KP * DM + idx;
    Wh[o] = hi;  Wl[o] = lo;
}

__global__ __launch_bounds__(256) void pack_x_kernel(
    const float* __restrict__ X, unsigned* __restrict__ Xh, unsigned* __restrict__ Xl)
{
    __shared__ unsigned smh[32 * 65];
    __shared__ unsigned sml[32 * 65];
    const int tid = threadIdx.x;
    const int m0 = blockIdx.x * 64, kp0 = blockIdx.y * 32;

    #pragma unroll
    for (int it = 0; it < 8; it++) {
        const int idx = it * 256 + tid;
        const int kp_l = idx & 31, m_l = idx >> 5;
        const float2 v = *reinterpret_cast<const float2*>(
            X + (size_t)(m0 + m_l) * DM + 2 * (kp0 + kp_l));
        unsigned hi, lo;
        bsplit2(v.x, v.y, hi, lo);
        smh[kp_l * 65 + m_l] = hi;
        sml[kp_l * 65 + m_l] = lo;
    }
    __syncthreads();
    #pragma unroll
    for (int it = 0; it < 8; it++) {
        const int idx = it * 256 + tid;
        const int kp_l = idx >> 6, m_l = idx & 63;
        Xh[(size_t)(kp0 + kp_l) * M_ROWS + m0 + m_l] = smh[kp_l * 65 + m_l];
        Xl[(size_t)(kp0 + kp_l) * M_ROWS + m0 + m_l] = sml[kp_l * 65 + m_l];
    }
}

// ---------------------------------------------------------------------------
// bf16x2 tensor-core GEMM: 256x128 tile, 512 threads (16 warps, 4x4 grid,
// 64x32 warp tiles). __launch_bounds__(512,2) -> 2 CTAs/SM (76.8KB x2 smem).
// A-array smem stride 264 (264 mod 32 == 8: same conflict-free pattern as 136).
// blockIdx.x>>3 selects weight/output: QKV fused grid (24, 32); out (8, 32).
// ---------------------------------------------------------------------------
#define SA 264
#define SB 136
#define ST_AH 0
#define ST_AL (8 * SA)                    // 2112
#define ST_BH (2 * 8 * SA)                // 4224
#define ST_BL (2 * 8 * SA + 8 * SB)       // 5312
#define STAGE_U32_G (2 * 8 * SA + 2 * 8 * SB)   // 6400
#define GEMM_SMEM_BYTES (3 * STAGE_U32_G * 4)   // 76800

template <bool HEAD_OUT>
__global__ __launch_bounds__(512, 2) void bf16x2_gemm_kernel(
    const unsigned* __restrict__ Ah, const unsigned* __restrict__ Al,
    const unsigned* __restrict__ Bh_base, const unsigned* __restrict__ Bl_base,
    float* __restrict__ C0, float* __restrict__ C1, float* __restrict__ C2,
    int M, int N)
{
    extern __shared__ unsigned sm[];

    const int tid  = threadIdx.x;
    const int bRow = blockIdx.y;              // 256-row block
    const int which = blockIdx.x >> 3;
    const int bCol = blockIdx.x & 7;
    const unsigned* Bh = Bh_base + (size_t)which * KP * DM;
    const unsigned* Bl = Bl_base + (size_t)which * KP * DM;
    float* C = (which == 0) ? C0 : ((which == 1) ? C1 : C2);

    const int wid = tid >> 5, lane = tid & 31;
    const int wm = wid >> 2, wn = wid & 3;    // 4x4 warps
    const int g  = lane >> 2, tg = lane & 3;

    // A loads: every thread does 1 CP16 for Ah and 1 for Al
    const int lrowA = tid >> 6;               // 0..7
    const int lsegA = tid & 63;               // x4 u32
    const size_t mA = (size_t)bRow * 256 + lsegA * 4;
    // B loads: threads [0,256) -> Bh, [256,512) -> Bl
    const int bt = tid & 255;
    const int lrowB = bt >> 5;                // 0..7
    const int lsegB = bt & 31;
    const size_t nB = (size_t)bCol * 128 + lsegB * 4;
    const bool doBh = tid < 256;

    const unsigned dst_base = (unsigned)__cvta_generic_to_shared(sm);

    auto issue = [&](int st, int s) {
        const unsigned stb = dst_base + st * STAGE_U32_G * 4;
        const size_t kprA = (size_t)(s * 8 + lrowA);
        CP16(stb + (ST_AH + lrowA * SA + lsegA * 4) * 4, Ah + kprA * M + mA);
        CP16(stb + (ST_AL + lrowA * SA + lsegA * 4) * 4, Al + kprA * M + mA);
        const size_t kprB = (size_t)(s * 8 + lrowB);
        if (doBh) CP16(stb + (ST_BH + lrowB * SB + lsegB * 4) * 4, Bh + kprB * N + nB);
        else      CP16(stb + (ST_BL + lrowB * SB + lsegB * 4) * 4, Bl + kprB * N + nB);
    };

    float acc[4][4][4] = {};

    issue(0, 0); CP_COMMIT();
    issue(1, 1); CP_COMMIT();

    const int NSLAB = 64;
    for (int s = 0; s < NSLAB; s++) {
        CP_WAIT1();
        __syncthreads();
        if (s + 2 < NSLAB) issue((s + 2) % 3, s + 2);
        CP_COMMIT();

        const unsigned* Sb  = sm + (s % 3) * STAGE_U32_G;
        const unsigned* SAh = Sb + ST_AH;
        const unsigned* SAl = Sb + ST_AL;
        const unsigned* SBh = Sb + ST_BH;
        const unsigned* SBl = Sb + ST_BL;

        unsigned a[4][4], bh[4][2], bl[4][2];
        #pragma unroll
        for (int mt = 0; mt < 4; mt++) {
            const int mrow = wm * 64 + mt * 16 + g;
            a[mt][0] = SAh[tg * SA + mrow];
            a[mt][1] = SAh[tg * SA + mrow + 8];
            a[mt][2] = SAh[(tg + 4) * SA + mrow];
            a[mt][3] = SAh[(tg + 4) * SA + mrow + 8];
        }
        #pragma unroll
        for (int nt = 0; nt < 4; nt++) {
            const int ncol = wn * 32 + nt * 8 + g;
            bh[nt][0] = SBh[tg * SB + ncol];
            bh[nt][1] = SBh[(tg + 4) * SB + ncol];
            bl[nt][0] = SBl[tg * SB + ncol];
            bl[nt][1] = SBl[(tg + 4) * SB + ncol];
        }
        #pragma unroll
        for (int mt = 0; mt < 4; mt++)
            #pragma unroll
            for (int nt = 0; nt < 4; nt++) mma_bf16(acc[mt][nt], a[mt], bh[nt]);
        #pragma unroll
        for (int mt = 0; mt < 4; mt++)
            #pragma unroll
            for (int nt = 0; nt < 4; nt++) mma_bf16(acc[mt][nt], a[mt], bl[nt]);
        #pragma unroll
        for (int mt = 0; mt < 4; mt++) {
            const int mrow = wm * 64 + mt * 16 + g;
            a[mt][0] = SAl[tg * SA + mrow];
            a[mt][1] = SAl[tg * SA + mrow + 8];
            a[mt][2] = SAl[(tg + 4) * SA + mrow];
            a[mt][3] = SAl[(tg + 4) * SA + mrow + 8];
        }
        #pragma unroll
        for (int mt = 0; mt < 4; mt++)
            #pragma unroll
            for (int nt = 0; nt < 4; nt++) mma_bf16(acc[mt][nt], a[mt], bh[nt]);
    }

    #pragma unroll
    for (int mt = 0; mt < 4; mt++) {
        #pragma unroll
        for (int nt = 0; nt < 4; nt++) {
            const int n0 = bCol * 128 + wn * 32 + nt * 8 + 2 * tg;
            #pragma unroll
            for (int half = 0; half < 2; half++) {
                const int m = bRow * 256 + wm * 64 + mt * 16 + g + half * 8;
                float2 val = make_float2(acc[mt][nt][half * 2], acc[mt][nt][half * 2 + 1]);
                if (HEAD_OUT) {
                    const int b = m / Tsz, t = m % Tsz;
                    const int h = n0 >> 6, d = n0 & 63;
                    *reinterpret_cast<float2*>(
                        &C[(((size_t)(b * Hn + h)) * Tsz + t) * HDsz + d]) = val;
                } else {
                    *reinterpret_cast<float2*>(&C[(size_t)m * N + n0]) = val;
                }
            }
        }
    }
}

// ---------------------------------------------------------------------------
// featmap via tensor cores
// ---------------------------------------------------------------------------
#define FMS 136
#define FEAT_SMEM_BYTES ((4 * 32 * FMS + 128) * 4)

__global__ __launch_bounds__(256) void featmap_mma_kernel(
    const float* __restrict__ Wf)
{
    extern __shared__ unsigned fsm[];
    unsigned* Ah = fsm;
    unsigned* Al = Ah + 32 * FMS;
    unsigned* Bh = Al + 32 * FMS;
    unsigned* Bl = Bh + 32 * FMS;
    float*    sqs = (float*)(Bl + 32 * FMS);

    const float* in = (blockIdx.y == 0) ? g_q : g_k;
    float* out      = (blockIdx.y == 0) ? g_qp : g_kp;

    const int tid = threadIdx.x;
    const size_t row0 = (size_t)blockIdx.x * 128;

    {
        const int m    = tid >> 1;
        const int halfc = (tid & 1) * 32;
        float vals[32];
        const float* src = in + (row0 + m) * HDsz + halfc;
        #pragma unroll
        for (int i = 0; i < 8; i++) {
            float4 v4 = *reinterpret_cast<const float4*>(src + i * 4);
            vals[i * 4 + 0] = v4.x; vals[i * 4 + 1] = v4.y;
            vals[i * 4 + 2] = v4.z; vals[i * 4 + 3] = v4.w;
        }
        float ss = 0.f;
        #pragma unroll
        for (int i = 0; i < 32; i++) ss += vals[i] * vals[i];
        ss += __shfl_xor_sync(0xffffffffu, ss, 1);
        if ((tid & 1) == 0) sqs[m] = 0.5f * ss;

        const int kp0 = (tid & 1) * 16;
        #pragma unroll
        for (int p = 0; p < 16; p++) {
            unsigned hi, lo;
            bsplit2(vals[2 * p], vals[2 * p + 1], hi, lo);
            Ah[(kp0 + p) * FMS + m] = hi;
            Al[(kp0 + p) * FMS + m] = lo;
        }
    }
    #pragma unroll
    for (int it = 0; it < 16; it++) {
        const int e = it * 256 + tid;
        const int kp = e >> 7, n = e & 127;
        unsigned hi, lo;
        bsplit2(Wf[(size_t)(2 * kp) * NFsz + n], Wf[(size_t)(2 * kp + 1) * NFsz + n], hi, lo);
        Bh[kp * FMS + n] = hi;
        Bl[kp * FMS + n] = lo;
    }
    __syncthreads();

    const int wid = tid >> 5, lane = tid & 31;
    const int wm = wid >> 2, wn = wid & 3;
    const int g  = lane >> 2, tg = lane & 3;

    float acc[4][4][4] = {};
    #pragma unroll
    for (int s = 0; s < 4; s++) {
        const int k0 = s * 8;
        unsigned a[4][4], bh[4][2], bl[4][2];
        #pragma unroll
        for (int nt = 0; nt < 4; nt++) {
            const int ncol = wn * 32 + nt * 8 + g;
            bh[nt][0] = Bh[(k0 + tg) * FMS + ncol];
            bh[nt][1] = Bh[(k0 + tg + 4) * FMS + ncol];
            bl[nt][0] = Bl[(k0 + tg) * FMS + ncol];
            bl[nt][1] = Bl[(k0 + tg + 4) * FMS + ncol];
        }
        #pragma unroll
        for (int mt = 0; mt < 4; mt++) {
            const int mrow = wm * 64 + mt * 16 + g;
            a[mt][0] = Ah[(k0 + tg) * FMS + mrow];
            a[mt][1] = Ah[(k0 + tg) * FMS + mrow + 8];
            a[mt][2] = Ah[(k0 + tg + 4) * FMS + mrow];
            a[mt][3] = Ah[(k0 + tg + 4) * FMS + mrow + 8];
        }
        #pragma unroll
        for (int mt = 0; mt < 4; mt++)
            #pragma unroll
            for (int nt = 0; nt < 4; nt++) mma_bf16(acc[mt][nt], a[mt], bh[nt]);
        #pragma unroll
        for (int mt = 0; mt < 4; mt++)
            #pragma unroll
            for (int nt = 0; nt < 4; nt++) mma_bf16(acc[mt][nt], a[mt], bl[nt]);
        #pragma unroll
        for (int mt = 0; mt < 4; mt++) {
            const int mrow = wm * 64 + mt * 16 + g;
            a[mt][0] = Al[(k0 + tg) * FMS + mrow];
            a[mt][1] = Al[(k0 + tg) * FMS + mrow + 8];
            a[mt][2] = Al[(k0 + tg + 4) * FMS + mrow];
            a[mt][3] = Al[(k0 + tg + 4) * FMS + mrow + 8];
        }
        #pragma unroll
        for (int mt = 0; mt < 4; mt++)
            #pragma unroll
            for (int nt = 0; nt < 4; nt++) mma_bf16(acc[mt][nt], a[mt], bh[nt]);
        #pragma unroll
        for (int mt = 0; mt < 4; mt++)
            #pragma unroll
            for (int nt = 0; nt < 4; nt++) mma_bf16(acc[mt][nt], a[mt], bl[nt]);
    }

    #pragma unroll
    for (int mt = 0; mt < 4; mt++) {
        #pragma unroll
        for (int nt = 0; nt < 4; nt++) {
            const int n0 = wn * 32 + nt * 8 + 2 * tg;
            #pragma unroll
            for (int half = 0; half < 2; half++) {
                const int rl = wm * 64 + mt * 16 + g + half * 8;
                const float sq = sqs[rl];
                float2 val;
                val.x = expf(acc[mt][nt][half * 2]     - sq) * INV_SQRT_NF;
                val.y = expf(acc[mt][nt][half * 2 + 1] - sq) * INV_SQRT_NF;
                *reinterpret_cast<float2*>(&out[(row0 + rl) * NFsz + n0]) = val;
            }
        }
    }
}

// ---------------------------------------------------------------------------
// chunk_sums via HMMA; z computed from packed smem (no global reload)
// ---------------------------------------------------------------------------
#define CS_SMEM_U32 (2 * 32 * 136 + 2 * 32 * 72)
#define CS_SMEM_BYTES (CS_SMEM_U32 * 4)

__global__ __launch_bounds__(256) void chunk_sums_mma_kernel()
{
    extern __shared__ unsigned csm[];
    unsigned* KAh = csm;
    unsigned* KAl = KAh + 32 * 136;
    unsigned* VBh = KAl + 32 * 136;
    unsigned* VBl = VBh + 32 * 72;

    const int c = blockIdx.x, bh = blockIdx.y;
    const int tid = threadIdx.x;

    const float* kp = g_kp + (size_t)(bh * Tsz + c * CH) * NFsz;
    const float* vv = g_v  + (size_t)(bh * Tsz + c * CH) * HDsz;

    {
        const int d = tid & 127, pg = tid >> 7;
        #pragma unroll
        for (int pp = 0; pp < 16; pp++) {
            const int p = pg * 16 + pp;
            const float a = kp[(size_t)(2 * p) * NFsz + d];
            const float b = kp[(size_t)(2 * p + 1) * NFsz + d];
            unsigned hi, lo;
            bsplit2(a, b, hi, lo);
            KAh[p * 136 + d] = hi;
            KAl[p * 136 + d] = lo;
        }
    }
    {
        const int e = tid & 63, pg = tid >> 6;
        #pragma unroll
        for (int pp = 0; pp < 8; pp++) {
            const int p = pg * 8 + pp;
            const float a = vv[(size_t)(2 * p) * HDsz + e];
            const float b = vv[(size_t)(2 * p + 1) * HDsz + e];
            unsigned hi, lo;
            bsplit2(a, b, hi, lo);
            VBh[p * 72 + e] = hi;
            VBl[p * 72 + e] = lo;
        }
    }
    __syncthreads();

    // z = colsum(kp) reconstructed from packed smem (err ~2^-17)
    if (tid < NFsz) {
        float s = 0.f;
        #pragma unroll 8
        for (int p = 0; p < 32; p++) {
            const unsigned h = KAh[p * 136 + tid], l = KAl[p * 136 + tid];
            s += (bf_lo(h) + bf_lo(l)) + (bf_hi(h) + bf_hi(l));
        }
        g_z[(size_t)(bh * NCH + c) * NFsz + tid] = s;
    }

    const int wid = tid >> 5, lane = tid & 31;
    const int wm = wid >> 1, wn = wid & 1;
    const int g  = lane >> 2, tg = lane & 3;

    float acc[2][4][4] = {};
    #pragma unroll
    for (int ks = 0; ks < 4; ks++) {
        const int k0 = ks * 8;
        unsigned a[2][4], bhf[4][2], blf[4][2];
        #pragma unroll
        for (int mt = 0; mt < 2; mt++) {
            const int mrow = wm * 32 + mt * 16 + g;
            a[mt][0] = KAh[(k0 + tg) * 136 + mrow];
            a[mt][1] = KAh[(k0 + tg) * 136 + mrow + 8];
            a[mt][2] = KAh[(k0 + tg + 4) * 136 + mrow];
            a[mt][3] = KAh[(k0 + tg + 4) * 136 + mrow + 8];
        }
        #pragma unroll
        for (int nt = 0; nt < 4; nt++) {
            const int ncol = wn * 32 + nt * 8 + g;
            bhf[nt][0] = VBh[(k0 + tg) * 72 + ncol];
            bhf[nt][1] = VBh[(k0 + tg + 4) * 72 + ncol];
            blf[nt][0] = VBl[(k0 + tg) * 72 + ncol];
            blf[nt][1] = VBl[(k0 + tg + 4) * 72 + ncol];
        }
        #pragma unroll
        for (int mt = 0; mt < 2; mt++)
            #pragma unroll
            for (int nt = 0; nt < 4; nt++) mma_bf16(acc[mt][nt], a[mt], bhf[nt]);
        #pragma unroll
        for (int mt = 0; mt < 2; mt++)
            #pragma unroll
            for (int nt = 0; nt < 4; nt++) mma_bf16(acc[mt][nt], a[mt], blf[nt]);
        #pragma unroll
        for (int mt = 0; mt < 2; mt++) {
            const int mrow = wm * 32 + mt * 16 + g;
            a[mt][0] = KAl[(k0 + tg) * 136 + mrow];
            a[mt][1] = KAl[(k0 + tg) * 136 + mrow + 8];
            a[mt][2] = KAl[(k0 + tg + 4) * 136 + mrow];
            a[mt][3] = KAl[(k0 + tg + 4) * 136 + mrow + 8];
        }
        #pragma unroll
        for (int mt = 0; mt < 2; mt++)
            #pragma unroll
            for (int nt = 0; nt < 4; nt++) mma_bf16(acc[mt][nt], a[mt], bhf[nt]);
    }

    float* Sout = g_S + (size_t)(bh * NCH + c) * NFsz * HDsz;
    #pragma unroll
    for (int mt = 0; mt < 2; mt++)
        #pragma unroll
        for (int nt = 0; nt < 4; nt++)
            #pragma unroll
            for (int half = 0; half < 2; half++) {
                const int d = wm * 32 + mt * 16 + g + half * 8;
                const int e = wn * 32 + nt * 8 + 2 * tg;
                *reinterpret_cast<float2*>(&Sout[d * HDsz + e]) =
                    make_float2(acc[mt][nt][half * 2], acc[mt][nt][half * 2 + 1]);
            }
}

// ---------------------------------------------------------------------------
// Pass 2: exclusive prefix
// ---------------------------------------------------------------------------
__global__ __launch_bounds__(256) void prefix_kernel()
{
    const int tid = blockIdx.x * 256 + threadIdx.x;
    const int total = BHn * (NFsz * HDsz + NFsz);
    if (tid >= total) return;
    const int bh = tid / (NFsz * HDsz + NFsz);
    const int r  = tid % (NFsz * HDsz + NFsz);
    float acc = 0.f;
    if (r < NFsz * HDsz) {
        float* p = g_S + (size_t)bh * NCH * NFsz * HDsz + r;
        for (int c = 0; c < NCH; c++) {
            float t = p[(size_t)c * NFsz * HDsz];
            p[(size_t)c * NFsz * HDsz] = acc;
            acc += t;
        }
    } else {
        float* p = g_z + (size_t)bh * NCH * NFsz + (r - NFsz * HDsz);
        for (int c = 0; c < NCH; c++) {
            float t = p[c * NFsz];
            p[c * NFsz] = acc;
            acc += t;
        }
    }
}

// ---------------------------------------------------------------------------
// chunk_out via HMMA
// ---------------------------------------------------------------------------
#define CO_QA   0
#define CO_KB   (2 * 64 * 72)
#define CO_SB   (CO_KB + 2 * 64 * 72)
#define CO_VB   (CO_SB + 2 * 64 * 72)
#define CO_ZD   (CO_VB + 2 * 32 * 72)
#define CO_SMEM_U32 (CO_ZD + 192)
#define CO_SMEM_BYTES (CO_SMEM_U32 * 4)

__global__ __launch_bounds__(256) void chunk_out_mma_kernel()
{
    extern __shared__ unsigned osm[];
    unsigned* QAh = osm + CO_QA;
    unsigned* QAl = QAh + 64 * 72;
    unsigned* KBh = osm + CO_KB;
    unsigned* KBl = KBh + 64 * 72;
    unsigned* SBh = osm + CO_SB;
    unsigned* SBl = SBh + 64 * 72;
    unsigned* VBh = osm + CO_VB;
    unsigned* VBl = VBh + 32 * 72;
    float*    z_s   = (float*)(osm + CO_ZD);
    float*    den_s = (float*)(osm + CO_ZD + 128);
    float*    A_s = (float*)(osm + CO_KB);
    unsigned* Ahp = osm + CO_KB + 4224;
    unsigned* Alp = Ahp + 32 * 72;

    const int c = blockIdx.x, bh = blockIdx.y;
    const int tid = threadIdx.x;

    const float* qp = g_qp + (size_t)(bh * Tsz + c * CH) * NFsz;
    const float* kp = g_kp + (size_t)(bh * Tsz + c * CH) * NFsz;
    const float* vv = g_v  + (size_t)(bh * Tsz + c * CH) * HDsz;
    const float* Sg = g_S  + (size_t)(bh * NCH + c) * NFsz * HDsz;
    const float* zg = g_z  + (size_t)(bh * NCH + c) * NFsz;

    {
        const int m = tid >> 2, qt = tid & 3;
        const float* qrow = qp + (size_t)m * NFsz + qt * 32;
        const float* krow = kp + (size_t)m * NFsz + qt * 32;
        #pragma unroll
        for (int i = 0; i < 8; i++) {
            float4 f = *reinterpret_cast<const float4*>(qrow + i * 4);
            const int p = qt * 16 + i * 2;
            unsigned hi, lo;
            bsplit2(f.x, f.y, hi, lo);
            QAh[p * 72 + m] = hi;  QAl[p * 72 + m] = lo;
            bsplit2(f.z, f.w, hi, lo);
            QAh[(p + 1) * 72 + m] = hi;  QAl[(p + 1) * 72 + m] = lo;
        }
        #pragma unroll
        for (int i = 0; i < 8; i++) {
            float4 f = *reinterpret_cast<const float4*>(krow + i * 4);
            const int p = qt * 16 + i * 2;
            unsigned hi, lo;
            bsplit2(f.x, f.y, hi, lo);
            KBh[p * 72 + m] = hi;  KBl[p * 72 + m] = lo;
            bsplit2(f.z, f.w, hi, lo);
            KBh[(p + 1) * 72 + m] = hi;  KBl[(p + 1) * 72 + m] = lo;
        }
    }
    {
        const int e = tid & 63, pg = tid >> 6;
        #pragma unroll
        for (int pp = 0; pp < 16; pp++) {
            const int p = pg * 16 + pp;
            const float a = Sg[(size_t)(2 * p) * HDsz + e];
            const float b = Sg[(size_t)(2 * p + 1) * HDsz + e];
            unsigned hi, lo;
            bsplit2(a, b, hi, lo);
            SBh[p * 72 + e] = hi;  SBl[p * 72 + e] = lo;
        }
    }
    {
        const int e = tid & 63, pg = tid >> 6;
        #pragma unroll
        for (int pp = 0; pp < 8; pp++) {
            const int p = pg * 8 + pp;
            const float a = vv[(size_t)(2 * p) * HDsz + e];
            const float b = vv[(size_t)(2 * p + 1) * HDsz + e];
            unsigned hi, lo;
            bsplit2(a, b, hi, lo);
            VBh[p * 72 + e] = hi;  VBl[p * 72 + e] = lo;
        }
    }
    if (tid < NFsz) z_s[tid] = zg[tid];
    __syncthreads();

    const int wid = tid >> 5, lane = tid & 31;
    const int wm = wid >> 2, wn = wid & 3;
    const int g  = lane >> 2, tg = lane & 3;

    float accA[2][2][4] = {};
    #pragma unroll
    for (int ks = 0; ks < 8; ks++) {
        const int k0 = ks * 8;
        unsigned a[2][4], bhf[2][2], blf[2][2];
        #pragma unroll
        for (int mt = 0; mt < 2; mt++) {
            const int mrow = wm * 32 + mt * 16 + g;
            a[mt][0] = QAh[(k0 + tg) * 72 + mrow];
            a[mt][1] = QAh[(k0 + tg) * 72 + mrow + 8];
            a[mt][2] = QAh[(k0 + tg + 4) * 72 + mrow];
            a[mt][3] = QAh[(k0 + tg + 4) * 72 + mrow + 8];
        }
        #pragma unroll
        for (int nt = 0; nt < 2; nt++) {
            const int ncol = wn * 16 + nt * 8 + g;
            bhf[nt][0] = KBh[(k0 + tg) * 72 + ncol];
            bhf[nt][1] = KBh[(k0 + tg + 4) * 72 + ncol];
            blf[nt][0] = KBl[(k0 + tg) * 72 + ncol];
            blf[nt][1] = KBl[(k0 + tg + 4) * 72 + ncol];
        }
        #pragma unroll
        for (int mt = 0; mt < 2; mt++)
            #pragma unroll
            for (int nt = 0; nt < 2; nt++) mma_bf16(accA[mt][nt], a[mt], bhf[nt]);
        #pragma unroll
        for (int mt = 0; mt < 2; mt++)
            #pragma unroll
            for (int nt = 0; nt < 2; nt++) mma_bf16(accA[mt][nt], a[mt], blf[nt]);
        #pragma unroll
        for (int mt = 0; mt < 2; mt++) {
            const int mrow = wm * 32 + mt * 16 + g;
            a[mt][0] = QAl[(k0 + tg) * 72 + mrow];
            a[mt][1] = QAl[(k0 + tg) * 72 + mrow + 8];
            a[mt][2] = QAl[(k0 + tg + 4) * 72 + mrow];
            a[mt][3] = QAl[(k0 + tg + 4) * 72 + mrow + 8];
        }
        #pragma unroll
        for (int mt = 0; mt < 2; mt++)
            #pragma unroll
            for (int nt = 0; nt < 2; nt++) mma_bf16(accA[mt][nt], a[mt], bhf[nt]);
    }
    __syncthreads();

    #pragma unroll
    for (int mt = 0; mt < 2; mt++)
        #pragma unroll
        for (int nt = 0; nt < 2; nt++)
            #pragma unroll
            for (int half = 0; half < 2; half++) {
                const int i = wm * 32 + mt * 16 + g + half * 8;
                const int j0 = wn * 16 + nt * 8 + 2 * tg;
                A_s[i * 66 + j0]     = (j0     <= i) ? accA[mt][nt][half * 2]     : 0.f;
                A_s[i * 66 + j0 + 1] = (j0 + 1 <= i) ? accA[mt][nt][half * 2 + 1] : 0.f;
            }
    __syncthreads();

    if (tid < CH) {
        const int m = tid;
        float s = EPSv;
        for (int j = 0; j < CH; j++) s += A_s[m * 66 + j];
        #pragma unroll 8
        for (int p = 0; p < 64; p++) {
            const unsigned h = QAh[p * 72 + m], l = QAl[p * 72 + m];
            const float v0 = bf_lo(h) + bf_lo(l);
            const float v1 = bf_hi(h) + bf_hi(l);
            s += v0 * z_s[2 * p] + v1 * z_s[2 * p + 1];
        }
        den_s[m] = s;
    }
    {
        const int m = tid >> 2, qt = tid & 3;
        #pragma unroll
        for (int i = 0; i < 8; i++) {
            const int p = qt * 8 + i;
            const float a0 = A_s[m * 66 + 2 * p];
            const float a1 = A_s[m * 66 + 2 * p + 1];
            unsigned hi, lo;
            bsplit2(a0, a1, hi, lo);
            Ahp[p * 72 + m] = hi;  Alp[p * 72 + m] = lo;
        }
    }
    __syncthreads();

    float accB[2][2][4] = {};
    #pragma unroll
    for (int ks = 0; ks < 4; ks++) {
        const int k0 = ks * 8;
        unsigned a[2][4], bhf[2][2], blf[2][2];
        #pragma unroll
        for (int mt = 0; mt < 2; mt++) {
            const int mrow = wm * 32 + mt * 16 + g;
            a[mt][0] = Ahp[(k0 + tg) * 72 + mrow];
            a[mt][1] = Ahp[(k0 + tg) * 72 + mrow + 8];
            a[mt][2] = Ahp[(k0 + tg + 4) * 72 + mrow];
            a[mt][3] = Ahp[(k0 + tg + 4) * 72 + mrow + 8];
        }
        #pragma unroll
        for (int nt = 0; nt < 2; nt++) {
            const int ncol = wn * 16 + nt * 8 + g;
            bhf[nt][0] = VBh[(k0 + tg) * 72 + ncol];
            bhf[nt][1] = VBh[(k0 + tg + 4) * 72 + ncol];
            blf[nt][0] = VBl[(k0 + tg) * 72 + ncol];
            blf[nt][1] = VBl[(k0 + tg + 4) * 72 + ncol];
        }
        #pragma unroll
        for (int mt = 0; mt < 2; mt++)
            #pragma unroll
            for (int nt = 0; nt < 2; nt++) mma_bf16(accB[mt][nt], a[mt], bhf[nt]);
        #pragma unroll
        for (int mt = 0; mt < 2; mt++)
            #pragma unroll
            for (int nt = 0; nt < 2; nt++) mma_bf16(accB[mt][nt], a[mt], blf[nt]);
        #pragma unroll
        for (int mt = 0; mt < 2; mt++) {
            const int mrow = wm * 32 + mt * 16 + g;
            a[mt][0] = Alp[(k0 + tg) * 72 + mrow];
            a[mt][1] = Alp[(k0 + tg) * 72 + mrow + 8];
            a[mt][2] = Alp[(k0 + tg + 4) * 72 + mrow];
            a[mt][3] = Alp[(k0 + tg + 4) * 72 + mrow + 8];
        }
        #pragma unroll
        for (int mt = 0; mt < 2; mt++)
            #pragma unroll
            for (int nt = 0; nt < 2; nt++) mma_bf16(accB[mt][nt], a[mt], bhf[nt]);
    }
    #pragma unroll
    for (int ks = 0; ks < 8; ks++) {
        const int k0 = ks * 8;
        unsigned a[2][4], bhf[2][2], blf[2][2];
        #pragma unroll
        for (int mt = 0; mt < 2; mt++) {
            const int mrow = wm * 32 + mt * 16 + g;
            a[mt][0] = QAh[(k0 + tg) * 72 + mrow];
            a[mt][1] = QAh[(k0 + tg) * 72 + mrow + 8];
            a[mt][2] = QAh[(k0 + tg + 4) * 72 + mrow];
            a[mt][3] = QAh[(k0 + tg + 4) * 72 + mrow + 8];
        }
        #pragma unroll
        for (int nt = 0; nt < 2; nt++) {
            const int ncol = wn * 16 + nt * 8 + g;
            bhf[nt][0] = SBh[(k0 + tg) * 72 + ncol];
            bhf[nt][1] = SBh[(k0 + tg + 4) * 72 + ncol];
            blf[nt][0] = SBl[(k0 + tg) * 72 + ncol];
            blf[nt][1] = SBl[(k0 + tg + 4) * 72 + ncol];
        }
        #pragma unroll
        for (int mt = 0; mt < 2; mt++)
            #pragma unroll
            for (int nt = 0; nt < 2; nt++) mma_bf16(accB[mt][nt], a[mt], bhf[nt]);
        #pragma unroll
        for (int mt = 0; mt < 2; mt++)
            #pragma unroll
            for (int nt = 0; nt < 2; nt++) mma_bf16(accB[mt][nt], a[mt], blf[nt]);
        #pragma unroll
        for (int mt = 0; mt < 2; mt++) {
            const int mrow = wm * 32 + mt * 16 + g;
            a[mt][0] = QAl[(k0 + tg) * 72 + mrow];
            a[mt][1] = QAl[(k0 + tg) * 72 + mrow + 8];
            a[mt][2] = QAl[(k0 + tg + 4) * 72 + mrow];
            a[mt][3] = QAl[(k0 + tg + 4) * 72 + mrow + 8];
        }
        #pragma unroll
        for (int mt = 0; mt < 2; mt++)
            #pragma unroll
            for (int nt = 0; nt < 2; nt++) mma_bf16(accB[mt][nt], a[mt], bhf[nt]);
    }

    const int b = bh >> 4, h = bh & 15;
    #pragma unroll
    for (int mt = 0; mt < 2; mt++)
        #pragma unroll
        for (int nt = 0; nt < 2; nt++)
            #pragma unroll
            for (int half = 0; half < 2; half++) {
                const int i = wm * 32 + mt * 16 + g + half * 8;
                const int e0 = wn * 16 + nt * 8 + 2 * tg;
                const int t = c * CH + i;
                const float inv = 1.0f / den_s[i];
                float2 val = make_float2(accB[mt][nt][half * 2] * inv,
                                         accB[mt][nt][half * 2 + 1] * inv);
                *reinterpret_cast<float2*>(
                    &g_y[((size_t)(b * Tsz + t)) * (Hn * HDsz) + h * HDsz + e0]) = val;
            }
}

// ---------------------------------------------------------------------------
extern "C" void kernel_launch(void* const* d_in, const int* in_sizes, int n_in,
                              void* d_out, int out_size)
{
    const float* x  = (const float*)d_in[0];
    const float* Wq = (const float*)d_in[1];
    const float* Wk = (const float*)d_in[2];
    const float* Wv = (const float*)d_in[3];
    const float* Wo = (const float*)d_in[4];
    const float* Wf = (const float*)d_in[5];
    float* out = (float*)d_out;

    float *q, *k, *v, *y;
    unsigned *Xh, *Xl, *Wh, *Wl;
    cudaGetSymbolAddress((void**)&q,  g_q);
    cudaGetSymbolAddress((void**)&k,  g_k);
    cudaGetSymbolAddress((void**)&v,  g_v);
    cudaGetSymbolAddress((void**)&y,  g_y);
    cudaGetSymbolAddress((void**)&Xh, g_Xh);
    cudaGetSymbolAddress((void**)&Xl, g_Xl);
    cudaGetSymbolAddress((void**)&Wh, g_Wh);
    cudaGetSymbolAddress((void**)&Wl, g_Wl);

    cudaFuncSetAttribute(bf16x2_gemm_kernel<true>,
                         cudaFuncAttributeMaxDynamicSharedMemorySize, GEMM_SMEM_BYTES);
    cudaFuncSetAttribute(bf16x2_gemm_kernel<false>,
                         cudaFuncAttributeMaxDynamicSharedMemorySize, GEMM_SMEM_BYTES);
    cudaFuncSetAttribute(featmap_mma_kernel,
                         cudaFuncAttributeMaxDynamicSharedMemorySize, FEAT_SMEM_BYTES);
    cudaFuncSetAttribute(chunk_sums_mma_kernel,
                         cudaFuncAttributeMaxDynamicSharedMemorySize, CS_SMEM_BYTES);
    cudaFuncSetAttribute(chunk_out_mma_kernel,
                         cudaFuncAttributeMaxDynamicSharedMemorySize, CO_SMEM_BYTES);

    const int WSTRIDE = KP * DM;
    pack_w4_kernel<<<dim3((KP * DM) / 256, 4), 256>>>(Wq, Wk, Wv, Wo, Wh, Wl);
    pack_x_kernel<<<dim3(M_ROWS / 64, KP / 32), 256>>>(x, Xh, Xl);

    // fused QKV: 3 weights x 8 col-blocks, 32 row-blocks of 256
    bf16x2_gemm_kernel<true><<<dim3(24, M_ROWS / 256), 512, GEMM_SMEM_BYTES>>>(
        Xh, Xl, Wh, Wl, q, k, v, M_ROWS, DM);

    featmap_mma_kernel<<<dim3(FROWS / 128, 2), 256, FEAT_SMEM_BYTES>>>(Wf);

    chunk_sums_mma_kernel<<<dim3(NCH, BHn), 256, CS_SMEM_BYTES>>>();
    prefix_kernel<<<2080, 256>>>();
    chunk_out_mma_kernel<<<dim3(NCH, BHn), 256, CO_SMEM_BYTES>>>();

    pack_x_kernel<<<dim3(M_ROWS / 64, KP / 32), 256>>>(y, Xh, Xl);
    bf16x2_gemm_kernel<false><<<dim3(8, M_ROWS / 256), 512, GEMM_SMEM_BYTES>>>(
        Xh, Xl, Wh + 3 * WSTRIDE, Wl + 3 * WSTRIDE, out, out, out, M_ROWS, DM);
}

// round 15
// speedup vs baseline: 2.4455x; 2.4455x over previous
#include <cuda_runtime.h>
#include <cuda_bf16.h>
#include <stdint.h>
#include <math.h>

// Problem constants
#define Bsz   4
#define Tsz   2048
#define DM    1024
#define Hn    16
#define HDsz  64
#define NFsz  128
#define CH    64
#define NCH   (Tsz / CH)      // 32
#define BHn   (Bsz * Hn)      // 64
#define EPSv  1e-6f
#define INV_SQRT_NF 0.08838834764831845f

#define M_ROWS (Bsz * Tsz)    // 8192
#define KP     (DM / 2)       // 512
#define FROWS  (BHn * Tsz)    // 131072

// -------------------- scratch (device globals) -----------------------------
__device__ float g_q [BHn * Tsz * HDsz];
__device__ float g_k [BHn * Tsz * HDsz];
__device__ float g_v [BHn * Tsz * HDsz];
__device__ float g_qp[BHn * Tsz * NFsz];
__device__ float g_kp[BHn * Tsz * NFsz];
__device__ float g_S [BHn * NCH * NFsz * HDsz];
__device__ float g_z [BHn * NCH * NFsz];
__device__ float g_y [Bsz * Tsz * Hn * HDsz];

__device__ unsigned g_Xh[KP * M_ROWS];
__device__ unsigned g_Xl[KP * M_ROWS];
__device__ unsigned g_Wh[4 * KP * DM];
__device__ unsigned g_Wl[4 * KP * DM];

// ---------------------------------------------------------------------------
// helpers
// ---------------------------------------------------------------------------
__device__ __forceinline__ void bsplit2(float v0, float v1, unsigned& hi, unsigned& lo) {
    __nv_bfloat16 h0 = __float2bfloat16_rn(v0);
    __nv_bfloat16 h1 = __float2bfloat16_rn(v1);
    float r0 = v0 - __bfloat162float(h0);
    float r1 = v1 - __bfloat162float(h1);
    __nv_bfloat16 l0 = __float2bfloat16_rn(r0);
    __nv_bfloat16 l1 = __float2bfloat16_rn(r1);
    hi = ((unsigned)__bfloat16_as_ushort(h1) << 16) | __bfloat16_as_ushort(h0);
    lo = ((unsigned)__bfloat16_as_ushort(l1) << 16) | __bfloat16_as_ushort(l0);
}

__device__ __forceinline__ float bf_lo(unsigned u) {
    return __bfloat162float(__ushort_as_bfloat16((unsigned short)(u & 0xffffu)));
}
__device__ __forceinline__ float bf_hi(unsigned u) {
    return __bfloat162float(__ushort_as_bfloat16((unsigned short)(u >> 16)));
}

__device__ __forceinline__ void mma_bf16(float c[4], const unsigned a[4], const unsigned b[2]) {
    asm volatile(
        "mma.sync.aligned.m16n8k16.row.col.f32.bf16.bf16.f32 "
        "{%0,%1,%2,%3}, {%4,%5,%6,%7}, {%8,%9}, {%0,%1,%2,%3};"
        : "+f"(c[0]), "+f"(c[1]), "+f"(c[2]), "+f"(c[3])
        : "r"(a[0]), "r"(a[1]), "r"(a[2]), "r"(a[3]), "r"(b[0]), "r"(b[1]));
}

#define CP16(dst, src) \
    asm volatile("cp.async.cg.shared.global [%0], [%1], 16;" :: "r"(dst), "l"(src))
#define CP_COMMIT() asm volatile("cp.async.commit_group;")
#define CP_WAIT1()  asm volatile("cp.async.wait_group 1;")

// ---------------------------------------------------------------------------
// pack_w (4 weights, one launch) / pack_x
// ---------------------------------------------------------------------------
__global__ __launch_bounds__(256) void pack_w4_kernel(
    const float* __restrict__ W0, const float* __restrict__ W1,
    const float* __restrict__ W2, const float* __restrict__ W3,
    unsigned* __restrict__ Wh, unsigned* __restrict__ Wl)
{
    const int w = blockIdx.y;
    const float* W = (w == 0) ? W0 : (w == 1) ? W1 : (w == 2) ? W2 : W3;
    const int idx = blockIdx.x * 256 + threadIdx.x;
    const int kp = idx >> 10, n = idx & 1023;
    const float v0 = W[(size_t)(2 * kp) * DM + n];
    const float v1 = W[(size_t)(2 * kp + 1) * DM + n];
    unsigned hi, lo;
    bsplit2(v0, v1, hi, lo);
    const size_t o = (size_t)w * KP * DM + idx;
    Wh[o] = hi;  Wl[o] = lo;
}

__global__ __launch_bounds__(256) void pack_x_kernel(
    const float* __restrict__ X, unsigned* __restrict__ Xh, unsigned* __restrict__ Xl)
{
    __shared__ unsigned smh[32 * 65];
    __shared__ unsigned sml[32 * 65];
    const int tid = threadIdx.x;
    const int m0 = blockIdx.x * 64, kp0 = blockIdx.y * 32;

    #pragma unroll
    for (int it = 0; it < 8; it++) {
        const int idx = it * 256 + tid;
        const int kp_l = idx & 31, m_l = idx >> 5;
        const float2 v = *reinterpret_cast<const float2*>(
            X + (size_t)(m0 + m_l) * DM + 2 * (kp0 + kp_l));
        unsigned hi, lo;
        bsplit2(v.x, v.y, hi, lo);
        smh[kp_l * 65 + m_l] = hi;
        sml[kp_l * 65 + m_l] = lo;
    }
    __syncthreads();
    #pragma unroll
    for (int it = 0; it < 8; it++) {
        const int idx = it * 256 + tid;
        const int kp_l = idx >> 6, m_l = idx & 63;
        Xh[(size_t)(kp0 + kp_l) * M_ROWS + m0 + m_l] = smh[kp_l * 65 + m_l];
        Xl[(size_t)(kp0 + kp_l) * M_ROWS + m0 + m_l] = sml[kp_l * 65 + m_l];
    }
}

// ---------------------------------------------------------------------------
// bf16x2 tensor-core GEMM (R13 proven config: 128x128, 256 thr, occ 2).
// blockIdx.x>>3 selects weight/output: QKV fused grid (24, 64); out (8, 64).
// ---------------------------------------------------------------------------
#define SMS 136
#define STAGE_U32 (4 * 8 * SMS)
#define GEMM_SMEM_BYTES (3 * STAGE_U32 * 4)

template <bool HEAD_OUT>
__global__ __launch_bounds__(256, 2) void bf16x2_gemm_kernel(
    const unsigned* __restrict__ Ah, const unsigned* __restrict__ Al,
    const unsigned* __restrict__ Bh_base, const unsigned* __restrict__ Bl_base,
    float* __restrict__ C0, float* __restrict__ C1, float* __restrict__ C2,
    int M, int N)
{
    extern __shared__ unsigned sm[];

    const int tid  = threadIdx.x;
    const int bRow = blockIdx.y;
    const int which = blockIdx.x >> 3;
    const int bCol = blockIdx.x & 7;
    const unsigned* Bh = Bh_base + (size_t)which * KP * DM;
    const unsigned* Bl = Bl_base + (size_t)which * KP * DM;
    float* C = (which == 0) ? C0 : ((which == 1) ? C1 : C2);

    const int wid = tid >> 5, lane = tid & 31;
    const int wm = wid >> 2, wn = wid & 3;
    const int g  = lane >> 2, tg = lane & 3;

    const int lrow = tid >> 5;
    const int lseg = tid & 31;
    const size_t mA = (size_t)bRow * 128 + lseg * 4;
    const size_t nB = (size_t)bCol * 128 + lseg * 4;

    const unsigned dst_base = (unsigned)__cvta_generic_to_shared(sm);
    const unsigned dst_off  = (lrow * SMS + lseg * 4) * 4;

    auto issue = [&](int st, int s) {
        const size_t kpr = (size_t)(s * 8 + lrow);
        const unsigned d0 = dst_base + st * STAGE_U32 * 4 + dst_off;
        CP16(d0,                Ah + kpr * M + mA);
        CP16(d0 + 8 * SMS * 4,  Al + kpr * M + mA);
        CP16(d0 + 16 * SMS * 4, Bh + kpr * N + nB);
        CP16(d0 + 24 * SMS * 4, Bl + kpr * N + nB);
    };

    float acc[4][4][4] = {};

    issue(0, 0); CP_COMMIT();
    issue(1, 1); CP_COMMIT();

    const int NSLAB = 64;
    for (int s = 0; s < NSLAB; s++) {
        CP_WAIT1();
        __syncthreads();
        if (s + 2 < NSLAB) issue((s + 2) % 3, s + 2);
        CP_COMMIT();

        const unsigned* Sb = sm + (s % 3) * STAGE_U32;
        const unsigned* SAh = Sb;
        const unsigned* SAl = Sb + 8 * SMS;
        const unsigned* SBh = Sb + 16 * SMS;
        const unsigned* SBl = Sb + 24 * SMS;

        unsigned a[4][4], bh[4][2], bl[4][2];
        #pragma unroll
        for (int mt = 0; mt < 4; mt++) {
            const int mrow = wm * 64 + mt * 16 + g;
            a[mt][0] = SAh[tg * SMS + mrow];
            a[mt][1] = SAh[tg * SMS + mrow + 8];
            a[mt][2] = SAh[(tg + 4) * SMS + mrow];
            a[mt][3] = SAh[(tg + 4) * SMS + mrow + 8];
        }
        #pragma unroll
        for (int nt = 0; nt < 4; nt++) {
            const int ncol = wn * 32 + nt * 8 + g;
            bh[nt][0] = SBh[tg * SMS + ncol];
            bh[nt][1] = SBh[(tg + 4) * SMS + ncol];
            bl[nt][0] = SBl[tg * SMS + ncol];
            bl[nt][1] = SBl[(tg + 4) * SMS + ncol];
        }
        #pragma unroll
        for (int mt = 0; mt < 4; mt++)
            #pragma unroll
            for (int nt = 0; nt < 4; nt++) mma_bf16(acc[mt][nt], a[mt], bh[nt]);
        #pragma unroll
        for (int mt = 0; mt < 4; mt++)
            #pragma unroll
            for (int nt = 0; nt < 4; nt++) mma_bf16(acc[mt][nt], a[mt], bl[nt]);
        #pragma unroll
        for (int mt = 0; mt < 4; mt++) {
            const int mrow = wm * 64 + mt * 16 + g;
            a[mt][0] = SAl[tg * SMS + mrow];
            a[mt][1] = SAl[tg * SMS + mrow + 8];
            a[mt][2] = SAl[(tg + 4) * SMS + mrow];
            a[mt][3] = SAl[(tg + 4) * SMS + mrow + 8];
        }
        #pragma unroll
        for (int mt = 0; mt < 4; mt++)
            #pragma unroll
            for (int nt = 0; nt < 4; nt++) mma_bf16(acc[mt][nt], a[mt], bh[nt]);
    }

    #pragma unroll
    for (int mt = 0; mt < 4; mt++) {
        #pragma unroll
        for (int nt = 0; nt < 4; nt++) {
            const int n0 = bCol * 128 + wn * 32 + nt * 8 + 2 * tg;
            #pragma unroll
            for (int half = 0; half < 2; half++) {
                const int m = bRow * 128 + wm * 64 + mt * 16 + g + half * 8;
                float2 val = make_float2(acc[mt][nt][half * 2], acc[mt][nt][half * 2 + 1]);
                if (HEAD_OUT) {
                    const int b = m / Tsz, t = m % Tsz;
                    const int h = n0 >> 6, d = n0 & 63;
                    *reinterpret_cast<float2*>(
                        &C[(((size_t)(b * Hn + h)) * Tsz + t) * HDsz + d]) = val;
                } else {
                    *reinterpret_cast<float2*>(&C[(size_t)m * N + n0]) = val;
                }
            }
        }
    }
}

// ---------------------------------------------------------------------------
// featmap via tensor cores
// ---------------------------------------------------------------------------
#define FMS 136
#define FEAT_SMEM_BYTES ((4 * 32 * FMS + 128) * 4)

__global__ __launch_bounds__(256) void featmap_mma_kernel(
    const float* __restrict__ Wf)
{
    extern __shared__ unsigned fsm[];
    unsigned* Ah = fsm;
    unsigned* Al = Ah + 32 * FMS;
    unsigned* Bh = Al + 32 * FMS;
    unsigned* Bl = Bh + 32 * FMS;
    float*    sqs = (float*)(Bl + 32 * FMS);

    const float* in = (blockIdx.y == 0) ? g_q : g_k;
    float* out      = (blockIdx.y == 0) ? g_qp : g_kp;

    const int tid = threadIdx.x;
    const size_t row0 = (size_t)blockIdx.x * 128;

    {
        const int m    = tid >> 1;
        const int halfc = (tid & 1) * 32;
        float vals[32];
        const float* src = in + (row0 + m) * HDsz + halfc;
        #pragma unroll
        for (int i = 0; i < 8; i++) {
            float4 v4 = *reinterpret_cast<const float4*>(src + i * 4);
            vals[i * 4 + 0] = v4.x; vals[i * 4 + 1] = v4.y;
            vals[i * 4 + 2] = v4.z; vals[i * 4 + 3] = v4.w;
        }
        float ss = 0.f;
        #pragma unroll
        for (int i = 0; i < 32; i++) ss += vals[i] * vals[i];
        ss += __shfl_xor_sync(0xffffffffu, ss, 1);
        if ((tid & 1) == 0) sqs[m] = 0.5f * ss;

        const int kp0 = (tid & 1) * 16;
        #pragma unroll
        for (int p = 0; p < 16; p++) {
            unsigned hi, lo;
            bsplit2(vals[2 * p], vals[2 * p + 1], hi, lo);
            Ah[(kp0 + p) * FMS + m] = hi;
            Al[(kp0 + p) * FMS + m] = lo;
        }
    }
    #pragma unroll
    for (int it = 0; it < 16; it++) {
        const int e = it * 256 + tid;
        const int kp = e >> 7, n = e & 127;
        unsigned hi, lo;
        bsplit2(Wf[(size_t)(2 * kp) * NFsz + n], Wf[(size_t)(2 * kp + 1) * NFsz + n], hi, lo);
        Bh[kp * FMS + n] = hi;
        Bl[kp * FMS + n] = lo;
    }
    __syncthreads();

    const int wid = tid >> 5, lane = tid & 31;
    const int wm = wid >> 2, wn = wid & 3;
    const int g  = lane >> 2, tg = lane & 3;

    float acc[4][4][4] = {};
    #pragma unroll
    for (int s = 0; s < 4; s++) {
        const int k0 = s * 8;
        unsigned a[4][4], bh[4][2], bl[4][2];
        #pragma unroll
        for (int nt = 0; nt < 4; nt++) {
            const int ncol = wn * 32 + nt * 8 + g;
            bh[nt][0] = Bh[(k0 + tg) * FMS + ncol];
            bh[nt][1] = Bh[(k0 + tg + 4) * FMS + ncol];
            bl[nt][0] = Bl[(k0 + tg) * FMS + ncol];
            bl[nt][1] = Bl[(k0 + tg + 4) * FMS + ncol];
        }
        #pragma unroll
        for (int mt = 0; mt < 4; mt++) {
            const int mrow = wm * 64 + mt * 16 + g;
            a[mt][0] = Ah[(k0 + tg) * FMS + mrow];
            a[mt][1] = Ah[(k0 + tg) * FMS + mrow + 8];
            a[mt][2] = Ah[(k0 + tg + 4) * FMS + mrow];
            a[mt][3] = Ah[(k0 + tg + 4) * FMS + mrow + 8];
        }
        #pragma unroll
        for (int mt = 0; mt < 4; mt++)
            #pragma unroll
            for (int nt = 0; nt < 4; nt++) mma_bf16(acc[mt][nt], a[mt], bh[nt]);
        #pragma unroll
        for (int mt = 0; mt < 4; mt++)
            #pragma unroll
            for (int nt = 0; nt < 4; nt++) mma_bf16(acc[mt][nt], a[mt], bl[nt]);
        #pragma unroll
        for (int mt = 0; mt < 4; mt++) {
            const int mrow = wm * 64 + mt * 16 + g;
            a[mt][0] = Al[(k0 + tg) * FMS + mrow];
            a[mt][1] = Al[(k0 + tg) * FMS + mrow + 8];
            a[mt][2] = Al[(k0 + tg + 4) * FMS + mrow];
            a[mt][3] = Al[(k0 + tg + 4) * FMS + mrow + 8];
        }
        #pragma unroll
        for (int mt = 0; mt < 4; mt++)
            #pragma unroll
            for (int nt = 0; nt < 4; nt++) mma_bf16(acc[mt][nt], a[mt], bh[nt]);
        #pragma unroll
        for (int mt = 0; mt < 4; mt++)
            #pragma unroll
            for (int nt = 0; nt < 4; nt++) mma_bf16(acc[mt][nt], a[mt], bl[nt]);
    }

    #pragma unroll
    for (int mt = 0; mt < 4; mt++) {
        #pragma unroll
        for (int nt = 0; nt < 4; nt++) {
            const int n0 = wn * 32 + nt * 8 + 2 * tg;
            #pragma unroll
            for (int half = 0; half < 2; half++) {
                const int rl = wm * 64 + mt * 16 + g + half * 8;
                const float sq = sqs[rl];
                float2 val;
                val.x = expf(acc[mt][nt][half * 2]     - sq) * INV_SQRT_NF;
                val.y = expf(acc[mt][nt][half * 2 + 1] - sq) * INV_SQRT_NF;
                *reinterpret_cast<float2*>(&out[(row0 + rl) * NFsz + n0]) = val;
            }
        }
    }
}

// ---------------------------------------------------------------------------
// chunk_sums via HMMA; z from packed smem
// ---------------------------------------------------------------------------
#define CS_SMEM_U32 (2 * 32 * 136 + 2 * 32 * 72)
#define CS_SMEM_BYTES (CS_SMEM_U32 * 4)

__global__ __launch_bounds__(256) void chunk_sums_mma_kernel()
{
    extern __shared__ unsigned csm[];
    unsigned* KAh = csm;
    unsigned* KAl = KAh + 32 * 136;
    unsigned* VBh = KAl + 32 * 136;
    unsigned* VBl = VBh + 32 * 72;

    const int c = blockIdx.x, bh = blockIdx.y;
    const int tid = threadIdx.x;

    const float* kp = g_kp + (size_t)(bh * Tsz + c * CH) * NFsz;
    const float* vv = g_v  + (size_t)(bh * Tsz + c * CH) * HDsz;

    {
        const int d = tid & 127, pg = tid >> 7;
        #pragma unroll
        for (int pp = 0; pp < 16; pp++) {
            const int p = pg * 16 + pp;
            const float a = kp[(size_t)(2 * p) * NFsz + d];
            const float b = kp[(size_t)(2 * p + 1) * NFsz + d];
            unsigned hi, lo;
            bsplit2(a, b, hi, lo);
            KAh[p * 136 + d] = hi;
            KAl[p * 136 + d] = lo;
        }
    }
    {
        const int e = tid & 63, pg = tid >> 6;
        #pragma unroll
        for (int pp = 0; pp < 8; pp++) {
            const int p = pg * 8 + pp;
            const float a = vv[(size_t)(2 * p) * HDsz + e];
            const float b = vv[(size_t)(2 * p + 1) * HDsz + e];
            unsigned hi, lo;
            bsplit2(a, b, hi, lo);
            VBh[p * 72 + e] = hi;
            VBl[p * 72 + e] = lo;
        }
    }
    __syncthreads();

    // z = colsum(kp) reconstructed from packed smem (err ~2^-17)
    if (tid < NFsz) {
        float s = 0.f;
        #pragma unroll 8
        for (int p = 0; p < 32; p++) {
            const unsigned h = KAh[p * 136 + tid], l = KAl[p * 136 + tid];
            s += (bf_lo(h) + bf_lo(l)) + (bf_hi(h) + bf_hi(l));
        }
        g_z[(size_t)(bh * NCH + c) * NFsz + tid] = s;
    }

    const int wid = tid >> 5, lane = tid & 31;
    const int wm = wid >> 1, wn = wid & 1;
    const int g  = lane >> 2, tg = lane & 3;

    float acc[2][4][4] = {};
    #pragma unroll
    for (int ks = 0; ks < 4; ks++) {
        const int k0 = ks * 8;
        unsigned a[2][4], bhf[4][2], blf[4][2];
        #pragma unroll
        for (int mt = 0; mt < 2; mt++) {
            const int mrow = wm * 32 + mt * 16 + g;
            a[mt][0] = KAh[(k0 + tg) * 136 + mrow];
            a[mt][1] = KAh[(k0 + tg) * 136 + mrow + 8];
            a[mt][2] = KAh[(k0 + tg + 4) * 136 + mrow];
            a[mt][3] = KAh[(k0 + tg + 4) * 136 + mrow + 8];
        }
        #pragma unroll
        for (int nt = 0; nt < 4; nt++) {
            const int ncol = wn * 32 + nt * 8 + g;
            bhf[nt][0] = VBh[(k0 + tg) * 72 + ncol];
            bhf[nt][1] = VBh[(k0 + tg + 4) * 72 + ncol];
            blf[nt][0] = VBl[(k0 + tg) * 72 + ncol];
            blf[nt][1] = VBl[(k0 + tg + 4) * 72 + ncol];
        }
        #pragma unroll
        for (int mt = 0; mt < 2; mt++)
            #pragma unroll
            for (int nt = 0; nt < 4; nt++) mma_bf16(acc[mt][nt], a[mt], bhf[nt]);
        #pragma unroll
        for (int mt = 0; mt < 2; mt++)
            #pragma unroll
            for (int nt = 0; nt < 4; nt++) mma_bf16(acc[mt][nt], a[mt], blf[nt]);
        #pragma unroll
        for (int mt = 0; mt < 2; mt++) {
            const int mrow = wm * 32 + mt * 16 + g;
            a[mt][0] = KAl[(k0 + tg) * 136 + mrow];
            a[mt][1] = KAl[(k0 + tg) * 136 + mrow + 8];
            a[mt][2] = KAl[(k0 + tg + 4) * 136 + mrow];
            a[mt][3] = KAl[(k0 + tg + 4) * 136 + mrow + 8];
        }
        #pragma unroll
        for (int mt = 0; mt < 2; mt++)
            #pragma unroll
            for (int nt = 0; nt < 4; nt++) mma_bf16(acc[mt][nt], a[mt], bhf[nt]);
    }

    float* Sout = g_S + (size_t)(bh * NCH + c) * NFsz * HDsz;
    #pragma unroll
    for (int mt = 0; mt < 2; mt++)
        #pragma unroll
        for (int nt = 0; nt < 4; nt++)
            #pragma unroll
            for (int half = 0; half < 2; half++) {
                const int d = wm * 32 + mt * 16 + g + half * 8;
                const int e = wn * 32 + nt * 8 + 2 * tg;
                *reinterpret_cast<float2*>(&Sout[d * HDsz + e]) =
                    make_float2(acc[mt][nt][half * 2], acc[mt][nt][half * 2 + 1]);
            }
}

// ---------------------------------------------------------------------------
// Pass 2: exclusive prefix
// ---------------------------------------------------------------------------
__global__ __launch_bounds__(256) void prefix_kernel()
{
    const int tid = blockIdx.x * 256 + threadIdx.x;
    const int total = BHn * (NFsz * HDsz + NFsz);
    if (tid >= total) return;
    const int bh = tid / (NFsz * HDsz + NFsz);
    const int r  = tid % (NFsz * HDsz + NFsz);
    float acc = 0.f;
    if (r < NFsz * HDsz) {
        float* p = g_S + (size_t)bh * NCH * NFsz * HDsz + r;
        for (int c = 0; c < NCH; c++) {
            float t = p[(size_t)c * NFsz * HDsz];
            p[(size_t)c * NFsz * HDsz] = acc;
            acc += t;
        }
    } else {
        float* p = g_z + (size_t)bh * NCH * NFsz + (r - NFsz * HDsz);
        for (int c = 0; c < NCH; c++) {
            float t = p[c * NFsz];
            p[c * NFsz] = acc;
            acc += t;
        }
    }
}

// ---------------------------------------------------------------------------
// chunk_out via HMMA
// ---------------------------------------------------------------------------
#define CO_QA   0
#define CO_KB   (2 * 64 * 72)
#define CO_SB   (CO_KB + 2 * 64 * 72)
#define CO_VB   (CO_SB + 2 * 64 * 72)
#define CO_ZD   (CO_VB + 2 * 32 * 72)
#define CO_SMEM_U32 (CO_ZD + 192)
#define CO_SMEM_BYTES (CO_SMEM_U32 * 4)

__global__ __launch_bounds__(256) void chunk_out_mma_kernel()
{
    extern __shared__ unsigned osm[];
    unsigned* QAh = osm + CO_QA;
    unsigned* QAl = QAh + 64 * 72;
    unsigned* KBh = osm + CO_KB;
    unsigned* KBl = KBh + 64 * 72;
    unsigned* SBh = osm + CO_SB;
    unsigned* SBl = SBh + 64 * 72;
    unsigned* VBh = osm + CO_VB;
    unsigned* VBl = VBh + 32 * 72;
    float*    z_s   = (float*)(osm + CO_ZD);
    float*    den_s = (float*)(osm + CO_ZD + 128);
    float*    A_s = (float*)(osm + CO_KB);
    unsigned* Ahp = osm + CO_KB + 4224;
    unsigned* Alp = Ahp + 32 * 72;

    const int c = blockIdx.x, bh = blockIdx.y;
    const int tid = threadIdx.x;

    const float* qp = g_qp + (size_t)(bh * Tsz + c * CH) * NFsz;
    const float* kp = g_kp + (size_t)(bh * Tsz + c * CH) * NFsz;
    const float* vv = g_v  + (size_t)(bh * Tsz + c * CH) * HDsz;
    const float* Sg = g_S  + (size_t)(bh * NCH + c) * NFsz * HDsz;
    const float* zg = g_z  + (size_t)(bh * NCH + c) * NFsz;

    {
        const int m = tid >> 2, qt = tid & 3;
        const float* qrow = qp + (size_t)m * NFsz + qt * 32;
        const float* krow = kp + (size_t)m * NFsz + qt * 32;
        #pragma unroll
        for (int i = 0; i < 8; i++) {
            float4 f = *reinterpret_cast<const float4*>(qrow + i * 4);
            const int p = qt * 16 + i * 2;
            unsigned hi, lo;
            bsplit2(f.x, f.y, hi, lo);
            QAh[p * 72 + m] = hi;  QAl[p * 72 + m] = lo;
            bsplit2(f.z, f.w, hi, lo);
            QAh[(p + 1) * 72 + m] = hi;  QAl[(p + 1) * 72 + m] = lo;
        }
        #pragma unroll
        for (int i = 0; i < 8; i++) {
            float4 f = *reinterpret_cast<const float4*>(krow + i * 4);
            const int p = qt * 16 + i * 2;
            unsigned hi, lo;
            bsplit2(f.x, f.y, hi, lo);
            KBh[p * 72 + m] = hi;  KBl[p * 72 + m] = lo;
            bsplit2(f.z, f.w, hi, lo);
            KBh[(p + 1) * 72 + m] = hi;  KBl[(p + 1) * 72 + m] = lo;
        }
    }
    {
        const int e = tid & 63, pg = tid >> 6;
        #pragma unroll
        for (int pp = 0; pp < 16; pp++) {
            const int p = pg * 16 + pp;
            const float a = Sg[(size_t)(2 * p) * HDsz + e];
            const float b = Sg[(size_t)(2 * p + 1) * HDsz + e];
            unsigned hi, lo;
            bsplit2(a, b, hi, lo);
            SBh[p * 72 + e] = hi;  SBl[p * 72 + e] = lo;
        }
    }
    {
        const int e = tid & 63, pg = tid >> 6;
        #pragma unroll
        for (int pp = 0; pp < 8; pp++) {
            const int p = pg * 8 + pp;
            const float a = vv[(size_t)(2 * p) * HDsz + e];
            const float b = vv[(size_t)(2 * p + 1) * HDsz + e];
            unsigned hi, lo;
            bsplit2(a, b, hi, lo);
            VBh[p * 72 + e] = hi;  VBl[p * 72 + e] = lo;
        }
    }
    if (tid < NFsz) z_s[tid] = zg[tid];
    __syncthreads();

    const int wid = tid >> 5, lane = tid & 31;
    const int wm = wid >> 2, wn = wid & 3;
    const int g  = lane >> 2, tg = lane & 3;

    float accA[2][2][4] = {};
    #pragma unroll
    for (int ks = 0; ks < 8; ks++) {
        const int k0 = ks * 8;
        unsigned a[2][4], bhf[2][2], blf[2][2];
        #pragma unroll
        for (int mt = 0; mt < 2; mt++) {
            const int mrow = wm * 32 + mt * 16 + g;
            a[mt][0] = QAh[(k0 + tg) * 72 + mrow];
            a[mt][1] = QAh[(k0 + tg) * 72 + mrow + 8];
            a[mt][2] = QAh[(k0 + tg + 4) * 72 + mrow];
            a[mt][3] = QAh[(k0 + tg + 4) * 72 + mrow + 8];
        }
        #pragma unroll
        for (int nt = 0; nt < 2; nt++) {
            const int ncol = wn * 16 + nt * 8 + g;
            bhf[nt][0] = KBh[(k0 + tg) * 72 + ncol];
            bhf[nt][1] = KBh[(k0 + tg + 4) * 72 + ncol];
            blf[nt][0] = KBl[(k0 + tg) * 72 + ncol];
            blf[nt][1] = KBl[(k0 + tg + 4) * 72 + ncol];
        }
        #pragma unroll
        for (int mt = 0; mt < 2; mt++)
            #pragma unroll
            for (int nt = 0; nt < 2; nt++) mma_bf16(accA[mt][nt], a[mt], bhf[nt]);
        #pragma unroll
        for (int mt = 0; mt < 2; mt++)
            #pragma unroll
            for (int nt = 0; nt < 2; nt++) mma_bf16(accA[mt][nt], a[mt], blf[nt]);
        #pragma unroll
        for (int mt = 0; mt < 2; mt++) {
            const int mrow = wm * 32 + mt * 16 + g;
            a[mt][0] = QAl[(k0 + tg) * 72 + mrow];
            a[mt][1] = QAl[(k0 + tg) * 72 + mrow + 8];
            a[mt][2] = QAl[(k0 + tg + 4) * 72 + mrow];
            a[mt][3] = QAl[(k0 + tg + 4) * 72 + mrow + 8];
        }
        #pragma unroll
        for (int mt = 0; mt < 2; mt++)
            #pragma unroll
            for (int nt = 0; nt < 2; nt++) mma_bf16(accA[mt][nt], a[mt], bhf[nt]);
    }
    __syncthreads();

    #pragma unroll
    for (int mt = 0; mt < 2; mt++)
        #pragma unroll
        for (int nt = 0; nt < 2; nt++)
            #pragma unroll
            for (int half = 0; half < 2; half++) {
                const int i = wm * 32 + mt * 16 + g + half * 8;
                const int j0 = wn * 16 + nt * 8 + 2 * tg;
                A_s[i * 66 + j0]     = (j0     <= i) ? accA[mt][nt][half * 2]     : 0.f;
                A_s[i * 66 + j0 + 1] = (j0 + 1 <= i) ? accA[mt][nt][half * 2 + 1] : 0.f;
            }
    __syncthreads();

    if (tid < CH) {
        const int m = tid;
        float s = EPSv;
        for (int j = 0; j < CH; j++) s += A_s[m * 66 + j];
        #pragma unroll 8
        for (int p = 0; p < 64; p++) {
            const unsigned h = QAh[p * 72 + m], l = QAl[p * 72 + m];
            const float v0 = bf_lo(h) + bf_lo(l);
            const float v1 = bf_hi(h) + bf_hi(l);
            s += v0 * z_s[2 * p] + v1 * z_s[2 * p + 1];
        }
        den_s[m] = s;
    }
    {
        const int m = tid >> 2, qt = tid & 3;
        #pragma unroll
        for (int i = 0; i < 8; i++) {
            const int p = qt * 8 + i;
            const float a0 = A_s[m * 66 + 2 * p];
            const float a1 = A_s[m * 66 + 2 * p + 1];
            unsigned hi, lo;
            bsplit2(a0, a1, hi, lo);
            Ahp[p * 72 + m] = hi;  Alp[p * 72 + m] = lo;
        }
    }
    __syncthreads();

    float accB[2][2][4] = {};
    #pragma unroll
    for (int ks = 0; ks < 4; ks++) {
        const int k0 = ks * 8;
        unsigned a[2][4], bhf[2][2], blf[2][2];
        #pragma unroll
        for (int mt = 0; mt < 2; mt++) {
            const int mrow = wm * 32 + mt * 16 + g;
            a[mt][0] = Ahp[(k0 + tg) * 72 + mrow];
            a[mt][1] = Ahp[(k0 + tg) * 72 + mrow + 8];
            a[mt][2] = Ahp[(k0 + tg + 4) * 72 + mrow];
            a[mt][3] = Ahp[(k0 + tg + 4) * 72 + mrow + 8];
        }
        #pragma unroll
        for (int nt = 0; nt < 2; nt++) {
            const int ncol = wn * 16 + nt * 8 + g;
            bhf[nt][0] = VBh[(k0 + tg) * 72 + ncol];
            bhf[nt][1] = VBh[(k0 + tg + 4) * 72 + ncol];
            blf[nt][0] = VBl[(k0 + tg) * 72 + ncol];
            blf[nt][1] = VBl[(k0 + tg + 4) * 72 + ncol];
        }
        #pragma unroll
        for (int mt = 0; mt < 2; mt++)
            #pragma unroll
            for (int nt = 0; nt < 2; nt++) mma_bf16(accB[mt][nt], a[mt], bhf[nt]);
        #pragma unroll
        for (int mt = 0; mt < 2; mt++)
            #pragma unroll
            for (int nt = 0; nt < 2; nt++) mma_bf16(accB[mt][nt], a[mt], blf[nt]);
        #pragma unroll
        for (int mt = 0; mt < 2; mt++) {
            const int mrow = wm * 32 + mt * 16 + g;
            a[mt][0] = Alp[(k0 + tg) * 72 + mrow];
            a[mt][1] = Alp[(k0 + tg) * 72 + mrow + 8];
            a[mt][2] = Alp[(k0 + tg + 4) * 72 + mrow];
            a[mt][3] = Alp[(k0 + tg + 4) * 72 + mrow + 8];
        }
        #pragma unroll
        for (int mt = 0; mt < 2; mt++)
            #pragma unroll
            for (int nt = 0; nt < 2; nt++) mma_bf16(accB[mt][nt], a[mt], bhf[nt]);
    }
    #pragma unroll
    for (int ks = 0; ks < 8; ks++) {
        const int k0 = ks * 8;
        unsigned a[2][4], bhf[2][2], blf[2][2];
        #pragma unroll
        for (int mt = 0; mt < 2; mt++) {
            const int mrow = wm * 32 + mt * 16 + g;
            a[mt][0] = QAh[(k0 + tg) * 72 + mrow];
            a[mt][1] = QAh[(k0 + tg) * 72 + mrow + 8];
            a[mt][2] = QAh[(k0 + tg + 4) * 72 + mrow];
            a[mt][3] = QAh[(k0 + tg + 4) * 72 + mrow + 8];
        }
        #pragma unroll
        for (int nt = 0; nt < 2; nt++) {
            const int ncol = wn * 16 + nt * 8 + g;
            bhf[nt][0] = SBh[(k0 + tg) * 72 + ncol];
            bhf[nt][1] = SBh[(k0 + tg + 4) * 72 + ncol];
            blf[nt][0] = SBl[(k0 + tg) * 72 + ncol];
            blf[nt][1] = SBl[(k0 + tg + 4) * 72 + ncol];
        }
        #pragma unroll
        for (int mt = 0; mt < 2; mt++)
            #pragma unroll
            for (int nt = 0; nt < 2; nt++) mma_bf16(accB[mt][nt], a[mt], bhf[nt]);
        #pragma unroll
        for (int mt = 0; mt < 2; mt++)
            #pragma unroll
            for (int nt = 0; nt < 2; nt++) mma_bf16(accB[mt][nt], a[mt], blf[nt]);
        #pragma unroll
        for (int mt = 0; mt < 2; mt++) {
            const int mrow = wm * 32 + mt * 16 + g;
            a[mt][0] = QAl[(k0 + tg) * 72 + mrow];
            a[mt][1] = QAl[(k0 + tg) * 72 + mrow + 8];
            a[mt][2] = QAl[(k0 + tg + 4) * 72 + mrow];
            a[mt][3] = QAl[(k0 + tg + 4) * 72 + mrow + 8];
        }
        #pragma unroll
        for (int mt = 0; mt < 2; mt++)
            #pragma unroll
            for (int nt = 0; nt < 2; nt++) mma_bf16(accB[mt][nt], a[mt], bhf[nt]);
    }

    const int b = bh >> 4, h = bh & 15;
    #pragma unroll
    for (int mt = 0; mt < 2; mt++)
        #pragma unroll
        for (int nt = 0; nt < 2; nt++)
            #pragma unroll
            for (int half = 0; half < 2; half++) {
                const int i = wm * 32 + mt * 16 + g + half * 8;
                const int e0 = wn * 16 + nt * 8 + 2 * tg;
                const int t = c * CH + i;
                const float inv = 1.0f / den_s[i];
                float2 val = make_float2(accB[mt][nt][half * 2] * inv,
                                         accB[mt][nt][half * 2 + 1] * inv);
                *reinterpret_cast<float2*>(
                    &g_y[((size_t)(b * Tsz + t)) * (Hn * HDsz) + h * HDsz + e0]) = val;
            }
}

// ---------------------------------------------------------------------------
extern "C" void kernel_launch(void* const* d_in, const int* in_sizes, int n_in,
                              void* d_out, int out_size)
{
    const float* x  = (const float*)d_in[0];
    const float* Wq = (const float*)d_in[1];
    const float* Wk = (const float*)d_in[2];
    const float* Wv = (const float*)d_in[3];
    const float* Wo = (const float*)d_in[4];
    const float* Wf = (const float*)d_in[5];
    float* out = (float*)d_out;

    float *q, *k, *v, *y;
    unsigned *Xh, *Xl, *Wh, *Wl;
    cudaGetSymbolAddress((void**)&q,  g_q);
    cudaGetSymbolAddress((void**)&k,  g_k);
    cudaGetSymbolAddress((void**)&v,  g_v);
    cudaGetSymbolAddress((void**)&y,  g_y);
    cudaGetSymbolAddress((void**)&Xh, g_Xh);
    cudaGetSymbolAddress((void**)&Xl, g_Xl);
    cudaGetSymbolAddress((void**)&Wh, g_Wh);
    cudaGetSymbolAddress((void**)&Wl, g_Wl);

    cudaFuncSetAttribute(bf16x2_gemm_kernel<true>,
                         cudaFuncAttributeMaxDynamicSharedMemorySize, GEMM_SMEM_BYTES);
    cudaFuncSetAttribute(bf16x2_gemm_kernel<false>,
                         cudaFuncAttributeMaxDynamicSharedMemorySize, GEMM_SMEM_BYTES);
    cudaFuncSetAttribute(featmap_mma_kernel,
                         cudaFuncAttributeMaxDynamicSharedMemorySize, FEAT_SMEM_BYTES);
    cudaFuncSetAttribute(chunk_sums_mma_kernel,
                         cudaFuncAttributeMaxDynamicSharedMemorySize, CS_SMEM_BYTES);
    cudaFuncSetAttribute(chunk_out_mma_kernel,
                         cudaFuncAttributeMaxDynamicSharedMemorySize, CO_SMEM_BYTES);

    const int WSTRIDE = KP * DM;
    pack_w4_kernel<<<dim3((KP * DM) / 256, 4), 256>>>(Wq, Wk, Wv, Wo, Wh, Wl);
    pack_x_kernel<<<dim3(M_ROWS / 64, KP / 32), 256>>>(x, Xh, Xl);

    // fused QKV: 3 weights x 8 col-blocks
    bf16x2_gemm_kernel<true><<<dim3(24, M_ROWS / 128), 256, GEMM_SMEM_BYTES>>>(
        Xh, Xl, Wh, Wl, q, k, v, M_ROWS, DM);

    featmap_mma_kernel<<<dim3(FROWS / 128, 2), 256, FEAT_SMEM_BYTES>>>(Wf);

    chunk_sums_mma_kernel<<<dim3(NCH, BHn), 256, CS_SMEM_BYTES>>>();
    prefix_kernel<<<2080, 256>>>();
    chunk_out_mma_kernel<<<dim3(NCH, BHn), 256, CO_SMEM_BYTES>>>();

    pack_x_kernel<<<dim3(M_ROWS / 64, KP / 32), 256>>>(y, Xh, Xl);
    bf16x2_gemm_kernel<false><<<dim3(8, M_ROWS / 128), 256, GEMM_SMEM_BYTES>>>(
        Xh, Xl, Wh + 3 * WSTRIDE, Wl + 3 * WSTRIDE, out, out, out, M_ROWS, DM);
}

// round 17
// speedup vs baseline: 2.4842x; 1.0158x over previous
#include <cuda_runtime.h>
#include <cuda_bf16.h>
#include <stdint.h>
#include <math.h>

// Problem constants
#define Bsz   4
#define Tsz   2048
#define DM    1024
#define Hn    16
#define HDsz  64
#define NFsz  128
#define CH    64
#define NCH   (Tsz / CH)      // 32
#define BHn   (Bsz * Hn)      // 64
#define EPSv  1e-6f
#define INV_SQRT_NF 0.08838834764831845f

#define M_ROWS (Bsz * Tsz)    // 8192
#define KP     (DM / 2)       // 512
#define FROWS  (BHn * Tsz)    // 131072

// -------------------- scratch (device globals) -----------------------------
__device__ float g_q [BHn * Tsz * HDsz];
__device__ float g_k [BHn * Tsz * HDsz];
__device__ float g_v [BHn * Tsz * HDsz];
__device__ float g_qp[BHn * Tsz * NFsz];
__device__ float g_kp[BHn * Tsz * NFsz];
__device__ float g_S [BHn * NCH * NFsz * HDsz];
__device__ float g_z [BHn * NCH * NFsz];

__device__ unsigned g_Xh[KP * M_ROWS];
__device__ unsigned g_Xl[KP * M_ROWS];
__device__ unsigned g_Wh[4 * KP * DM];
__device__ unsigned g_Wl[4 * KP * DM];
__device__ unsigned g_Fh[32 * NFsz];     // packed Wf hi, [kp][n]
__device__ unsigned g_Fl[32 * NFsz];     // packed Wf lo

// ---------------------------------------------------------------------------
// helpers
// ---------------------------------------------------------------------------
__device__ __forceinline__ void bsplit2(float v0, float v1, unsigned& hi, unsigned& lo) {
    __nv_bfloat16 h0 = __float2bfloat16_rn(v0);
    __nv_bfloat16 h1 = __float2bfloat16_rn(v1);
    float r0 = v0 - __bfloat162float(h0);
    float r1 = v1 - __bfloat162float(h1);
    __nv_bfloat16 l0 = __float2bfloat16_rn(r0);
    __nv_bfloat16 l1 = __float2bfloat16_rn(r1);
    hi = ((unsigned)__bfloat16_as_ushort(h1) << 16) | __bfloat16_as_ushort(h0);
    lo = ((unsigned)__bfloat16_as_ushort(l1) << 16) | __bfloat16_as_ushort(l0);
}

__device__ __forceinline__ float bf_lo(unsigned u) {
    return __bfloat162float(__ushort_as_bfloat16((unsigned short)(u & 0xffffu)));
}
__device__ __forceinline__ float bf_hi(unsigned u) {
    return __bfloat162float(__ushort_as_bfloat16((unsigned short)(u >> 16)));
}

__device__ __forceinline__ void mma_bf16(float c[4], const unsigned a[4], const unsigned b[2]) {
    asm volatile(
        "mma.sync.aligned.m16n8k16.row.col.f32.bf16.bf16.f32 "
        "{%0,%1,%2,%3}, {%4,%5,%6,%7}, {%8,%9}, {%0,%1,%2,%3};"
        : "+f"(c[0]), "+f"(c[1]), "+f"(c[2]), "+f"(c[3])
        : "r"(a[0]), "r"(a[1]), "r"(a[2]), "r"(a[3]), "r"(b[0]), "r"(b[1]));
}

#define CP16(dst, src) \
    asm volatile("cp.async.cg.shared.global [%0], [%1], 16;" :: "r"(dst), "l"(src))
#define CP_COMMIT() asm volatile("cp.async.commit_group;")
#define CP_WAIT1()  asm volatile("cp.async.wait_group 1;")

// ---------------------------------------------------------------------------
// pack_w (4 weights, one launch) / pack_wf / pack_x
// ---------------------------------------------------------------------------
__global__ __launch_bounds__(256) void pack_w4_kernel(
    const float* __restrict__ W0, const float* __restrict__ W1,
    const float* __restrict__ W2, const float* __restrict__ W3,
    unsigned* __restrict__ Wh, unsigned* __restrict__ Wl)
{
    const int w = blockIdx.y;
    const float* W = (w == 0) ? W0 : (w == 1) ? W1 : (w == 2) ? W2 : W3;
    const int idx = blockIdx.x * 256 + threadIdx.x;
    const int kp = idx >> 10, n = idx & 1023;
    const float v0 = W[(size_t)(2 * kp) * DM + n];
    const float v1 = W[(size_t)(2 * kp + 1) * DM + n];
    unsigned hi, lo;
    bsplit2(v0, v1, hi, lo);
    const size_t o = (size_t)w * KP * DM + idx;
    Wh[o] = hi;  Wl[o] = lo;
}

__global__ __launch_bounds__(256) void pack_wf_kernel(const float* __restrict__ Wf)
{
    const int idx = blockIdx.x * 256 + threadIdx.x;   // over 32*128
    const int kp = idx >> 7, n = idx & 127;
    unsigned hi, lo;
    bsplit2(Wf[(size_t)(2 * kp) * NFsz + n], Wf[(size_t)(2 * kp + 1) * NFsz + n], hi, lo);
    g_Fh[idx] = hi;  g_Fl[idx] = lo;
}

__global__ __launch_bounds__(256) void pack_x_kernel(
    const float* __restrict__ X, unsigned* __restrict__ Xh, unsigned* __restrict__ Xl)
{
    __shared__ unsigned smh[32 * 65];
    __shared__ unsigned sml[32 * 65];
    const int tid = threadIdx.x;
    const int m0 = blockIdx.x * 64, kp0 = blockIdx.y * 32;

    #pragma unroll
    for (int it = 0; it < 8; it++) {
        const int idx = it * 256 + tid;
        const int kp_l = idx & 31, m_l = idx >> 5;
        const float2 v = *reinterpret_cast<const float2*>(
            X + (size_t)(m0 + m_l) * DM + 2 * (kp0 + kp_l));
        unsigned hi, lo;
        bsplit2(v.x, v.y, hi, lo);
        smh[kp_l * 65 + m_l] = hi;
        sml[kp_l * 65 + m_l] = lo;
    }
    __syncthreads();
    #pragma unroll
    for (int it = 0; it < 8; it++) {
        const int idx = it * 256 + tid;
        const int kp_l = idx >> 6, m_l = idx & 63;
        Xh[(size_t)(kp0 + kp_l) * M_ROWS + m0 + m_l] = smh[kp_l * 65 + m_l];
        Xl[(size_t)(kp0 + kp_l) * M_ROWS + m0 + m_l] = sml[kp_l * 65 + m_l];
    }
}

// ---------------------------------------------------------------------------
// bf16x2 tensor-core GEMM (proven config: 128x128, 256 thr, occ 2).
// blockIdx.x>>3 selects weight/output: QKV fused grid (24, 64); out (8, 64).
// ---------------------------------------------------------------------------
#define SMS 136
#define STAGE_U32 (4 * 8 * SMS)
#define GEMM_SMEM_BYTES (3 * STAGE_U32 * 4)

template <bool HEAD_OUT>
__global__ __launch_bounds__(256, 2) void bf16x2_gemm_kernel(
    const unsigned* __restrict__ Ah, const unsigned* __restrict__ Al,
    const unsigned* __restrict__ Bh_base, const unsigned* __restrict__ Bl_base,
    float* __restrict__ C0, float* __restrict__ C1, float* __restrict__ C2,
    int M, int N)
{
    extern __shared__ unsigned sm[];

    const int tid  = threadIdx.x;
    const int bRow = blockIdx.y;
    const int which = blockIdx.x >> 3;
    const int bCol = blockIdx.x & 7;
    const unsigned* Bh = Bh_base + (size_t)which * KP * DM;
    const unsigned* Bl = Bl_base + (size_t)which * KP * DM;
    float* C = (which == 0) ? C0 : ((which == 1) ? C1 : C2);

    const int wid = tid >> 5, lane = tid & 31;
    const int wm = wid >> 2, wn = wid & 3;
    const int g  = lane >> 2, tg = lane & 3;

    const int lrow = tid >> 5;
    const int lseg = tid & 31;
    const size_t mA = (size_t)bRow * 128 + lseg * 4;
    const size_t nB = (size_t)bCol * 128 + lseg * 4;

    const unsigned dst_base = (unsigned)__cvta_generic_to_shared(sm);
    const unsigned dst_off  = (lrow * SMS + lseg * 4) * 4;

    auto issue = [&](int st, int s) {
        const size_t kpr = (size_t)(s * 8 + lrow);
        const unsigned d0 = dst_base + st * STAGE_U32 * 4 + dst_off;
        CP16(d0,                Ah + kpr * M + mA);
        CP16(d0 + 8 * SMS * 4,  Al + kpr * M + mA);
        CP16(d0 + 16 * SMS * 4, Bh + kpr * N + nB);
        CP16(d0 + 24 * SMS * 4, Bl + kpr * N + nB);
    };

    float acc[4][4][4] = {};

    issue(0, 0); CP_COMMIT();
    issue(1, 1); CP_COMMIT();

    const int NSLAB = 64;
    for (int s = 0; s < NSLAB; s++) {
        CP_WAIT1();
        __syncthreads();
        if (s + 2 < NSLAB) issue((s + 2) % 3, s + 2);
        CP_COMMIT();

        const unsigned* Sb = sm + (s % 3) * STAGE_U32;
        const unsigned* SAh = Sb;
        const unsigned* SAl = Sb + 8 * SMS;
        const unsigned* SBh = Sb + 16 * SMS;
        const unsigned* SBl = Sb + 24 * SMS;

        unsigned a[4][4], bh[4][2], bl[4][2];
        #pragma unroll
        for (int mt = 0; mt < 4; mt++) {
            const int mrow = wm * 64 + mt * 16 + g;
            a[mt][0] = SAh[tg * SMS + mrow];
            a[mt][1] = SAh[tg * SMS + mrow + 8];
            a[mt][2] = SAh[(tg + 4) * SMS + mrow];
            a[mt][3] = SAh[(tg + 4) * SMS + mrow + 8];
        }
        #pragma unroll
        for (int nt = 0; nt < 4; nt++) {
            const int ncol = wn * 32 + nt * 8 + g;
            bh[nt][0] = SBh[tg * SMS + ncol];
            bh[nt][1] = SBh[(tg + 4) * SMS + ncol];
            bl[nt][0] = SBl[tg * SMS + ncol];
            bl[nt][1] = SBl[(tg + 4) * SMS + ncol];
        }
        #pragma unroll
        for (int mt = 0; mt < 4; mt++)
            #pragma unroll
            for (int nt = 0; nt < 4; nt++) mma_bf16(acc[mt][nt], a[mt], bh[nt]);
        #pragma unroll
        for (int mt = 0; mt < 4; mt++)
            #pragma unroll
            for (int nt = 0; nt < 4; nt++) mma_bf16(acc[mt][nt], a[mt], bl[nt]);
        #pragma unroll
        for (int mt = 0; mt < 4; mt++) {
            const int mrow = wm * 64 + mt * 16 + g;
            a[mt][0] = SAl[tg * SMS + mrow];
            a[mt][1] = SAl[tg * SMS + mrow + 8];
            a[mt][2] = SAl[(tg + 4) * SMS + mrow];
            a[mt][3] = SAl[(tg + 4) * SMS + mrow + 8];
        }
        #pragma unroll
        for (int mt = 0; mt < 4; mt++)
            #pragma unroll
            for (int nt = 0; nt < 4; nt++) mma_bf16(acc[mt][nt], a[mt], bh[nt]);
    }

    #pragma unroll
    for (int mt = 0; mt < 4; mt++) {
        #pragma unroll
        for (int nt = 0; nt < 4; nt++) {
            const int n0 = bCol * 128 + wn * 32 + nt * 8 + 2 * tg;
            #pragma unroll
            for (int half = 0; half < 2; half++) {
                const int m = bRow * 128 + wm * 64 + mt * 16 + g + half * 8;
                float2 val = make_float2(acc[mt][nt][half * 2], acc[mt][nt][half * 2 + 1]);
                if (HEAD_OUT) {
                    const int b = m / Tsz, t = m % Tsz;
                    const int h = n0 >> 6, d = n0 & 63;
                    *reinterpret_cast<float2*>(
                        &C[(((size_t)(b * Hn + h)) * Tsz + t) * HDsz + d]) = val;
                } else {
                    *reinterpret_cast<float2*>(&C[(size_t)m * N + n0]) = val;
                }
            }
        }
    }
}

// ---------------------------------------------------------------------------
// featmap via tensor cores; Wf pre-packed in g_Fh/g_Fl; 3-term split.
// ---------------------------------------------------------------------------
#define FMS 136
#define FEAT_SMEM_BYTES ((4 * 32 * FMS + 128) * 4)

__global__ __launch_bounds__(256) void featmap_mma_kernel()
{
    extern __shared__ unsigned fsm[];
    unsigned* Ah = fsm;
    unsigned* Al = Ah + 32 * FMS;
    unsigned* Bh = Al + 32 * FMS;
    unsigned* Bl = Bh + 32 * FMS;
    float*    sqs = (float*)(Bl + 32 * FMS);

    const float* in = (blockIdx.y == 0) ? g_q : g_k;
    float* out      = (blockIdx.y == 0) ? g_qp : g_kp;

    const int tid = threadIdx.x;
    const size_t row0 = (size_t)blockIdx.x * 128;

    {
        const int m    = tid >> 1;
        const int halfc = (tid & 1) * 32;
        float vals[32];
        const float* src = in + (row0 + m) * HDsz + halfc;
        #pragma unroll
        for (int i = 0; i < 8; i++) {
            float4 v4 = *reinterpret_cast<const float4*>(src + i * 4);
            vals[i * 4 + 0] = v4.x; vals[i * 4 + 1] = v4.y;
            vals[i * 4 + 2] = v4.z; vals[i * 4 + 3] = v4.w;
        }
        float ss = 0.f;
        #pragma unroll
        for (int i = 0; i < 32; i++) ss += vals[i] * vals[i];
        ss += __shfl_xor_sync(0xffffffffu, ss, 1);
        if ((tid & 1) == 0) sqs[m] = 0.5f * ss;

        const int kp0 = (tid & 1) * 16;
        #pragma unroll
        for (int p = 0; p < 16; p++) {
            unsigned hi, lo;
            bsplit2(vals[2 * p], vals[2 * p + 1], hi, lo);
            Ah[(kp0 + p) * FMS + m] = hi;
            Al[(kp0 + p) * FMS + m] = lo;
        }
    }
    // Wf already packed: straight copy into padded smem
    #pragma unroll
    for (int it = 0; it < 16; it++) {
        const int e = it * 256 + tid;
        const int kp = e >> 7, n = e & 127;
        Bh[kp * FMS + n] = g_Fh[e];
        Bl[kp * FMS + n] = g_Fl[e];
    }
    __syncthreads();

    const int wid = tid >> 5, lane = tid & 31;
    const int wm = wid >> 2, wn = wid & 3;
    const int g  = lane >> 2, tg = lane & 3;

    float acc[4][4][4] = {};
    #pragma unroll
    for (int s = 0; s < 4; s++) {
        const int k0 = s * 8;
        unsigned a[4][4], bh[4][2], bl[4][2];
        #pragma unroll
        for (int nt = 0; nt < 4; nt++) {
            const int ncol = wn * 32 + nt * 8 + g;
            bh[nt][0] = Bh[(k0 + tg) * FMS + ncol];
            bh[nt][1] = Bh[(k0 + tg + 4) * FMS + ncol];
            bl[nt][0] = Bl[(k0 + tg) * FMS + ncol];
            bl[nt][1] = Bl[(k0 + tg + 4) * FMS + ncol];
        }
        #pragma unroll
        for (int mt = 0; mt < 4; mt++) {
            const int mrow = wm * 64 + mt * 16 + g;
            a[mt][0] = Ah[(k0 + tg) * FMS + mrow];
            a[mt][1] = Ah[(k0 + tg) * FMS + mrow + 8];
            a[mt][2] = Ah[(k0 + tg + 4) * FMS + mrow];
            a[mt][3] = Ah[(k0 + tg + 4) * FMS + mrow + 8];
        }
        #pragma unroll
        for (int mt = 0; mt < 4; mt++)
            #pragma unroll
            for (int nt = 0; nt < 4; nt++) mma_bf16(acc[mt][nt], a[mt], bh[nt]);
        #pragma unroll
        for (int mt = 0; mt < 4; mt++)
            #pragma unroll
            for (int nt = 0; nt < 4; nt++) mma_bf16(acc[mt][nt], a[mt], bl[nt]);
        #pragma unroll
        for (int mt = 0; mt < 4; mt++) {
            const int mrow = wm * 64 + mt * 16 + g;
            a[mt][0] = Al[(k0 + tg) * FMS + mrow];
            a[mt][1] = Al[(k0 + tg) * FMS + mrow + 8];
            a[mt][2] = Al[(k0 + tg + 4) * FMS + mrow];
            a[mt][3] = Al[(k0 + tg + 4) * FMS + mrow + 8];
        }
        #pragma unroll
        for (int mt = 0; mt < 4; mt++)
            #pragma unroll
            for (int nt = 0; nt < 4; nt++) mma_bf16(acc[mt][nt], a[mt], bh[nt]);
    }

    #pragma unroll
    for (int mt = 0; mt < 4; mt++) {
        #pragma unroll
        for (int nt = 0; nt < 4; nt++) {
            const int n0 = wn * 32 + nt * 8 + 2 * tg;
            #pragma unroll
            for (int half = 0; half < 2; half++) {
                const int rl = wm * 64 + mt * 16 + g + half * 8;
                const float sq = sqs[rl];
                float2 val;
                val.x = expf(acc[mt][nt][half * 2]     - sq) * INV_SQRT_NF;
                val.y = expf(acc[mt][nt][half * 2 + 1] - sq) * INV_SQRT_NF;
                *reinterpret_cast<float2*>(&out[(row0 + rl) * NFsz + n0]) = val;
            }
        }
    }
}

// ---------------------------------------------------------------------------
// chunk_sums via HMMA; z from packed smem
// ---------------------------------------------------------------------------
#define CS_SMEM_U32 (2 * 32 * 136 + 2 * 32 * 72)
#define CS_SMEM_BYTES (CS_SMEM_U32 * 4)

__global__ __launch_bounds__(256) void chunk_sums_mma_kernel()
{
    extern __shared__ unsigned csm[];
    unsigned* KAh = csm;
    unsigned* KAl = KAh + 32 * 136;
    unsigned* VBh = KAl + 32 * 136;
    unsigned* VBl = VBh + 32 * 72;

    const int c = blockIdx.x, bh = blockIdx.y;
    const int tid = threadIdx.x;

    const float* kp = g_kp + (size_t)(bh * Tsz + c * CH) * NFsz;
    const float* vv = g_v  + (size_t)(bh * Tsz + c * CH) * HDsz;

    {
        const int d = tid & 127, pg = tid >> 7;
        #pragma unroll
        for (int pp = 0; pp < 16; pp++) {
            const int p = pg * 16 + pp;
            const float a = kp[(size_t)(2 * p) * NFsz + d];
            const float b = kp[(size_t)(2 * p + 1) * NFsz + d];
            unsigned hi, lo;
            bsplit2(a, b, hi, lo);
            KAh[p * 136 + d] = hi;
            KAl[p * 136 + d] = lo;
        }
    }
    {
        const int e = tid & 63, pg = tid >> 6;
        #pragma unroll
        for (int pp = 0; pp < 8; pp++) {
            const int p = pg * 8 + pp;
            const float a = vv[(size_t)(2 * p) * HDsz + e];
            const float b = vv[(size_t)(2 * p + 1) * HDsz + e];
            unsigned hi, lo;
            bsplit2(a, b, hi, lo);
            VBh[p * 72 + e] = hi;
            VBl[p * 72 + e] = lo;
        }
    }
    __syncthreads();

    if (tid < NFsz) {
        float s = 0.f;
        #pragma unroll 8
        for (int p = 0; p < 32; p++) {
            const unsigned h = KAh[p * 136 + tid], l = KAl[p * 136 + tid];
            s += (bf_lo(h) + bf_lo(l)) + (bf_hi(h) + bf_hi(l));
        }
        g_z[(size_t)(bh * NCH + c) * NFsz + tid] = s;
    }

    const int wid = tid >> 5, lane = tid & 31;
    const int wm = wid >> 1, wn = wid & 1;
    const int g  = lane >> 2, tg = lane & 3;

    float acc[2][4][4] = {};
    #pragma unroll
    for (int ks = 0; ks < 4; ks++) {
        const int k0 = ks * 8;
        unsigned a[2][4], bhf[4][2], blf[4][2];
        #pragma unroll
        for (int mt = 0; mt < 2; mt++) {
            const int mrow = wm * 32 + mt * 16 + g;
            a[mt][0] = KAh[(k0 + tg) * 136 + mrow];
            a[mt][1] = KAh[(k0 + tg) * 136 + mrow + 8];
            a[mt][2] = KAh[(k0 + tg + 4) * 136 + mrow];
            a[mt][3] = KAh[(k0 + tg + 4) * 136 + mrow + 8];
        }
        #pragma unroll
        for (int nt = 0; nt < 4; nt++) {
            const int ncol = wn * 32 + nt * 8 + g;
            bhf[nt][0] = VBh[(k0 + tg) * 72 + ncol];
            bhf[nt][1] = VBh[(k0 + tg + 4) * 72 + ncol];
            blf[nt][0] = VBl[(k0 + tg) * 72 + ncol];
            blf[nt][1] = VBl[(k0 + tg + 4) * 72 + ncol];
        }
        #pragma unroll
        for (int mt = 0; mt < 2; mt++)
            #pragma unroll
            for (int nt = 0; nt < 4; nt++) mma_bf16(acc[mt][nt], a[mt], bhf[nt]);
        #pragma unroll
        for (int mt = 0; mt < 2; mt++)
            #pragma unroll
            for (int nt = 0; nt < 4; nt++) mma_bf16(acc[mt][nt], a[mt], blf[nt]);
        #pragma unroll
        for (int mt = 0; mt < 2; mt++) {
            const int mrow = wm * 32 + mt * 16 + g;
            a[mt][0] = KAl[(k0 + tg) * 136 + mrow];
            a[mt][1] = KAl[(k0 + tg) * 136 + mrow + 8];
            a[mt][2] = KAl[(k0 + tg + 4) * 136 + mrow];
            a[mt][3] = KAl[(k0 + tg + 4) * 136 + mrow + 8];
        }
        #pragma unroll
        for (int mt = 0; mt < 2; mt++)
            #pragma unroll
            for (int nt = 0; nt < 4; nt++) mma_bf16(acc[mt][nt], a[mt], bhf[nt]);
    }

    float* Sout = g_S + (size_t)(bh * NCH + c) * NFsz * HDsz;
    #pragma unroll
    for (int mt = 0; mt < 2; mt++)
        #pragma unroll
        for (int nt = 0; nt < 4; nt++)
            #pragma unroll
            for (int half = 0; half < 2; half++) {
                const int d = wm * 32 + mt * 16 + g + half * 8;
                const int e = wn * 32 + nt * 8 + 2 * tg;
                *reinterpret_cast<float2*>(&Sout[d * HDsz + e]) =
                    make_float2(acc[mt][nt][half * 2], acc[mt][nt][half * 2 + 1]);
            }
}

// ---------------------------------------------------------------------------
// Pass 2: exclusive prefix
// ---------------------------------------------------------------------------
__global__ __launch_bounds__(256) void prefix_kernel()
{
    const int tid = blockIdx.x * 256 + threadIdx.x;
    const int total = BHn * (NFsz * HDsz + NFsz);
    if (tid >= total) return;
    const int bh = tid / (NFsz * HDsz + NFsz);
    const int r  = tid % (NFsz * HDsz + NFsz);
    float acc = 0.f;
    if (r < NFsz * HDsz) {
        float* p = g_S + (size_t)bh * NCH * NFsz * HDsz + r;
        for (int c = 0; c < NCH; c++) {
            float t = p[(size_t)c * NFsz * HDsz];
            p[(size_t)c * NFsz * HDsz] = acc;
            acc += t;
        }
    } else {
        float* p = g_z + (size_t)bh * NCH * NFsz + (r - NFsz * HDsz);
        for (int c = 0; c < NCH; c++) {
            float t = p[c * NFsz];
            p[c * NFsz] = acc;
            acc += t;
        }
    }
}

// ---------------------------------------------------------------------------
// chunk_out via HMMA; epilogue writes packed bf16 hi/lo directly into
// g_Xh/g_Xl ([kp][m] layout) so the out-proj GEMM needs no separate pack.
// ---------------------------------------------------------------------------
#define CO_QA   0
#define CO_KB   (2 * 64 * 72)
#define CO_SB   (CO_KB + 2 * 64 * 72)
#define CO_VB   (CO_SB + 2 * 64 * 72)
#define CO_ZD   (CO_VB + 2 * 32 * 72)
#define CO_SMEM_U32 (CO_ZD + 192)
#define CO_SMEM_BYTES (CO_SMEM_U32 * 4)

__global__ __launch_bounds__(256) void chunk_out_mma_kernel()
{
    extern __shared__ unsigned osm[];
    unsigned* QAh = osm + CO_QA;
    unsigned* QAl = QAh + 64 * 72;
    unsigned* KBh = osm + CO_KB;
    unsigned* KBl = KBh + 64 * 72;
    unsigned* SBh = osm + CO_SB;
    unsigned* SBl = SBh + 64 * 72;
    unsigned* VBh = osm + CO_VB;
    unsigned* VBl = VBh + 32 * 72;
    float*    z_s   = (float*)(osm + CO_ZD);
    float*    den_s = (float*)(osm + CO_ZD + 128);
    float*    A_s = (float*)(osm + CO_KB);
    unsigned* Ahp = osm + CO_KB + 4224;
    unsigned* Alp = Ahp + 32 * 72;

    const int c = blockIdx.x, bh = blockIdx.y;
    const int tid = threadIdx.x;

    const float* qp = g_qp + (size_t)(bh * Tsz + c * CH) * NFsz;
    const float* kp = g_kp + (size_t)(bh * Tsz + c * CH) * NFsz;
    const float* vv = g_v  + (size_t)(bh * Tsz + c * CH) * HDsz;
    const float* Sg = g_S  + (size_t)(bh * NCH + c) * NFsz * HDsz;
    const float* zg = g_z  + (size_t)(bh * NCH + c) * NFsz;

    {
        const int m = tid >> 2, qt = tid & 3;
        const float* qrow = qp + (size_t)m * NFsz + qt * 32;
        const float* krow = kp + (size_t)m * NFsz + qt * 32;
        #pragma unroll
        for (int i = 0; i < 8; i++) {
            float4 f = *reinterpret_cast<const float4*>(qrow + i * 4);
            const int p = qt * 16 + i * 2;
            unsigned hi, lo;
            bsplit2(f.x, f.y, hi, lo);
            QAh[p * 72 + m] = hi;  QAl[p * 72 + m] = lo;
            bsplit2(f.z, f.w, hi, lo);
            QAh[(p + 1) * 72 + m] = hi;  QAl[(p + 1) * 72 + m] = lo;
        }
        #pragma unroll
        for (int i = 0; i < 8; i++) {
            float4 f = *reinterpret_cast<const float4*>(krow + i * 4);
            const int p = qt * 16 + i * 2;
            unsigned hi, lo;
            bsplit2(f.x, f.y, hi, lo);
            KBh[p * 72 + m] = hi;  KBl[p * 72 + m] = lo;
            bsplit2(f.z, f.w, hi, lo);
            KBh[(p + 1) * 72 + m] = hi;  KBl[(p + 1) * 72 + m] = lo;
        }
    }
    {
        const int e = tid & 63, pg = tid >> 6;
        #pragma unroll
        for (int pp = 0; pp < 16; pp++) {
            const int p = pg * 16 + pp;
            const float a = Sg[(size_t)(2 * p) * HDsz + e];
            const float b = Sg[(size_t)(2 * p + 1) * HDsz + e];
            unsigned hi, lo;
            bsplit2(a, b, hi, lo);
            SBh[p * 72 + e] = hi;  SBl[p * 72 + e] = lo;
        }
    }
    {
        const int e = tid & 63, pg = tid >> 6;
        #pragma unroll
        for (int pp = 0; pp < 8; pp++) {
            const int p = pg * 8 + pp;
            const float a = vv[(size_t)(2 * p) * HDsz + e];
            const float b = vv[(size_t)(2 * p + 1) * HDsz + e];
            unsigned hi, lo;
            bsplit2(a, b, hi, lo);
            VBh[p * 72 + e] = hi;  VBl[p * 72 + e] = lo;
        }
    }
    if (tid < NFsz) z_s[tid] = zg[tid];
    __syncthreads();

    const int wid = tid >> 5, lane = tid & 31;
    const int wm = wid >> 2, wn = wid & 3;
    const int g  = lane >> 2, tg = lane & 3;

    float accA[2][2][4] = {};
    #pragma unroll
    for (int ks = 0; ks < 8; ks++) {
        const int k0 = ks * 8;
        unsigned a[2][4], bhf[2][2], blf[2][2];
        #pragma unroll
        for (int mt = 0; mt < 2; mt++) {
            const int mrow = wm * 32 + mt * 16 + g;
            a[mt][0] = QAh[(k0 + tg) * 72 + mrow];
            a[mt][1] = QAh[(k0 + tg) * 72 + mrow + 8];
            a[mt][2] = QAh[(k0 + tg + 4) * 72 + mrow];
            a[mt][3] = QAh[(k0 + tg + 4) * 72 + mrow + 8];
        }
        #pragma unroll
        for (int nt = 0; nt < 2; nt++) {
            const int ncol = wn * 16 + nt * 8 + g;
            bhf[nt][0] = KBh[(k0 + tg) * 72 + ncol];
            bhf[nt][1] = KBh[(k0 + tg + 4) * 72 + ncol];
            blf[nt][0] = KBl[(k0 + tg) * 72 + ncol];
            blf[nt][1] = KBl[(k0 + tg + 4) * 72 + ncol];
        }
        #pragma unroll
        for (int mt = 0; mt < 2; mt++)
            #pragma unroll
            for (int nt = 0; nt < 2; nt++) mma_bf16(accA[mt][nt], a[mt], bhf[nt]);
        #pragma unroll
        for (int mt = 0; mt < 2; mt++)
            #pragma unroll
            for (int nt = 0; nt < 2; nt++) mma_bf16(accA[mt][nt], a[mt], blf[nt]);
        #pragma unroll
        for (int mt = 0; mt < 2; mt++) {
            const int mrow = wm * 32 + mt * 16 + g;
            a[mt][0] = QAl[(k0 + tg) * 72 + mrow];
            a[mt][1] = QAl[(k0 + tg) * 72 + mrow + 8];
            a[mt][2] = QAl[(k0 + tg + 4) * 72 + mrow];
            a[mt][3] = QAl[(k0 + tg + 4) * 72 + mrow + 8];
        }
        #pragma unroll
        for (int mt = 0; mt < 2; mt++)
            #pragma unroll
            for (int nt = 0; nt < 2; nt++) mma_bf16(accA[mt][nt], a[mt], bhf[nt]);
    }
    __syncthreads();

    #pragma unroll
    for (int mt = 0; mt < 2; mt++)
        #pragma unroll
        for (int nt = 0; nt < 2; nt++)
            #pragma unroll
            for (int half = 0; half < 2; half++) {
                const int i = wm * 32 + mt * 16 + g + half * 8;
                const int j0 = wn * 16 + nt * 8 + 2 * tg;
                A_s[i * 66 + j0]     = (j0     <= i) ? accA[mt][nt][half * 2]     : 0.f;
                A_s[i * 66 + j0 + 1] = (j0 + 1 <= i) ? accA[mt][nt][half * 2 + 1] : 0.f;
            }
    __syncthreads();

    if (tid < CH) {
        const int m = tid;
        float s = EPSv;
        for (int j = 0; j < CH; j++) s += A_s[m * 66 + j];
        #pragma unroll 8
        for (int p = 0; p < 64; p++) {
            const unsigned h = QAh[p * 72 + m], l = QAl[p * 72 + m];
            const float v0 = bf_lo(h) + bf_lo(l);
            const float v1 = bf_hi(h) + bf_hi(l);
            s += v0 * z_s[2 * p] + v1 * z_s[2 * p + 1];
        }
        den_s[m] = s;
    }
    {
        const int m = tid >> 2, qt = tid & 3;
        #pragma unroll
        for (int i = 0; i < 8; i++) {
            const int p = qt * 8 + i;
            const float a0 = A_s[m * 66 + 2 * p];
            const float a1 = A_s[m * 66 + 2 * p + 1];
            unsigned hi, lo;
            bsplit2(a0, a1, hi, lo);
            Ahp[p * 72 + m] = hi;  Alp[p * 72 + m] = lo;
        }
    }
    __syncthreads();

    float accB[2][2][4] = {};
    #pragma unroll
    for (int ks = 0; ks < 4; ks++) {
        const int k0 = ks * 8;
        unsigned a[2][4], bhf[2][2], blf[2][2];
        #pragma unroll
        for (int mt = 0; mt < 2; mt++) {
            const int mrow = wm * 32 + mt * 16 + g;
            a[mt][0] = Ahp[(k0 + tg) * 72 + mrow];
            a[mt][1] = Ahp[(k0 + tg) * 72 + mrow + 8];
            a[mt][2] = Ahp[(k0 + tg + 4) * 72 + mrow];
            a[mt][3] = Ahp[(k0 + tg + 4) * 72 + mrow + 8];
        }
        #pragma unroll
        for (int nt = 0; nt < 2; nt++) {
            const int ncol = wn * 16 + nt * 8 + g;
            bhf[nt][0] = VBh[(k0 + tg) * 72 + ncol];
            bhf[nt][1] = VBh[(k0 + tg + 4) * 72 + ncol];
            blf[nt][0] = VBl[(k0 + tg) * 72 + ncol];
            blf[nt][1] = VBl[(k0 + tg + 4) * 72 + ncol];
        }
        #pragma unroll
        for (int mt = 0; mt < 2; mt++)
            #pragma unroll
            for (int nt = 0; nt < 2; nt++) mma_bf16(accB[mt][nt], a[mt], bhf[nt]);
        #pragma unroll
        for (int mt = 0; mt < 2; mt++)
            #pragma unroll
            for (int nt = 0; nt < 2; nt++) mma_bf16(accB[mt][nt], a[mt], blf[nt]);
        #pragma unroll
        for (int mt = 0; mt < 2; mt++) {
            const int mrow = wm * 32 + mt * 16 + g;
            a[mt][0] = Alp[(k0 + tg) * 72 + mrow];
            a[mt][1] = Alp[(k0 + tg) * 72 + mrow + 8];
            a[mt][2] = Alp[(k0 + tg + 4) * 72 + mrow];
            a[mt][3] = Alp[(k0 + tg + 4) * 72 + mrow + 8];
        }
        #pragma unroll
        for (int mt = 0; mt < 2; mt++)
            #pragma unroll
            for (int nt = 0; nt < 2; nt++) mma_bf16(accB[mt][nt], a[mt], bhf[nt]);
    }
    #pragma unroll
    for (int ks = 0; ks < 8; ks++) {
        const int k0 = ks * 8;
        unsigned a[2][4], bhf[2][2], blf[2][2];
        #pragma unroll
        for (int mt = 0; mt < 2; mt++) {
            const int mrow = wm * 32 + mt * 16 + g;
            a[mt][0] = QAh[(k0 + tg) * 72 + mrow];
            a[mt][1] = QAh[(k0 + tg) * 72 + mrow + 8];
            a[mt][2] = QAh[(k0 + tg + 4) * 72 + mrow];
            a[mt][3] = QAh[(k0 + tg + 4) * 72 + mrow + 8];
        }
        #pragma unroll
        for (int nt = 0; nt < 2; nt++) {
            const int ncol = wn * 16 + nt * 8 + g;
            bhf[nt][0] = SBh[(k0 + tg) * 72 + ncol];
            bhf[nt][1] = SBh[(k0 + tg + 4) * 72 + ncol];
            blf[nt][0] = SBl[(k0 + tg) * 72 + ncol];
            blf[nt][1] = SBl[(k0 + tg + 4) * 72 + ncol];
        }
        #pragma unroll
        for (int mt = 0; mt < 2; mt++)
            #pragma unroll
            for (int nt = 0; nt < 2; nt++) mma_bf16(accB[mt][nt], a[mt], bhf[nt]);
        #pragma unroll
        for (int mt = 0; mt < 2; mt++)
            #pragma unroll
            for (int nt = 0; nt < 2; nt++) mma_bf16(accB[mt][nt], a[mt], blf[nt]);
        #pragma unroll
        for (int mt = 0; mt < 2; mt++) {
            const int mrow = wm * 32 + mt * 16 + g;
            a[mt][0] = QAl[(k0 + tg) * 72 + mrow];
            a[mt][1] = QAl[(k0 + tg) * 72 + mrow + 8];
            a[mt][2] = QAl[(k0 + tg + 4) * 72 + mrow];
            a[mt][3] = QAl[(k0 + tg + 4) * 72 + mrow + 8];
        }
        #pragma unroll
        for (int mt = 0; mt < 2; mt++)
            #pragma unroll
            for (int nt = 0; nt < 2; nt++) mma_bf16(accB[mt][nt], a[mt], bhf[nt]);
    }

    // epilogue: y = num/den, packed straight into g_Xh/g_Xl ([kp][m])
    const int b = bh >> 4, h = bh & 15;
    #pragma unroll
    for (int mt = 0; mt < 2; mt++)
        #pragma unroll
        for (int nt = 0; nt < 2; nt++)
            #pragma unroll
            for (int half = 0; half < 2; half++) {
                const int i = wm * 32 + mt * 16 + g + half * 8;
                const int e0 = wn * 16 + nt * 8 + 2 * tg;   // even
                const int t = c * CH + i;
                const float inv = 1.0f / den_s[i];
                const float v0 = accB[mt][nt][half * 2] * inv;
                const float v1 = accB[mt][nt][half * 2 + 1] * inv;
                unsigned hi, lo;
                bsplit2(v0, v1, hi, lo);
                const int kpg = h * 32 + (e0 >> 1);
                const size_t m = (size_t)b * Tsz + t;
                g_Xh[(size_t)kpg * M_ROWS + m] = hi;
                g_Xl[(size_t)kpg * M_ROWS + m] = lo;
            }
}

// ---------------------------------------------------------------------------
extern "C" void kernel_launch(void* const* d_in, const int* in_sizes, int n_in,
                              void* d_out, int out_size)
{
    const float* x  = (const float*)d_in[0];
    const float* Wq = (const float*)d_in[1];
    const float* Wk = (const float*)d_in[2];
    const float* Wv = (const float*)d_in[3];
    const float* Wo = (const float*)d_in[4];
    const float* Wf = (const float*)d_in[5];
    float* out = (float*)d_out;

    float *q, *k, *v;
    unsigned *Xh, *Xl, *Wh, *Wl;
    cudaGetSymbolAddress((void**)&q,  g_q);
    cudaGetSymbolAddress((void**)&k,  g_k);
    cudaGetSymbolAddress((void**)&v,  g_v);
    cudaGetSymbolAddress((void**)&Xh, g_Xh);
    cudaGetSymbolAddress((void**)&Xl, g_Xl);
    cudaGetSymbolAddress((void**)&Wh, g_Wh);
    cudaGetSymbolAddress((void**)&Wl, g_Wl);

    cudaFuncSetAttribute(bf16x2_gemm_kernel<true>,
                         cudaFuncAttributeMaxDynamicSharedMemorySize, GEMM_SMEM_BYTES);
    cudaFuncSetAttribute(bf16x2_gemm_kernel<false>,
                         cudaFuncAttributeMaxDynamicSharedMemorySize, GEMM_SMEM_BYTES);
    cudaFuncSetAttribute(featmap_mma_kernel,
                         cudaFuncAttributeMaxDynamicSharedMemorySize, FEAT_SMEM_BYTES);
    cudaFuncSetAttribute(chunk_sums_mma_kernel,
                         cudaFuncAttributeMaxDynamicSharedMemorySize, CS_SMEM_BYTES);
    cudaFuncSetAttribute(chunk_out_mma_kernel,
                         cudaFuncAttributeMaxDynamicSharedMemorySize, CO_SMEM_BYTES);

    const int WSTRIDE = KP * DM;
    pack_w4_kernel<<<dim3((KP * DM) / 256, 4), 256>>>(Wq, Wk, Wv, Wo, Wh, Wl);
    pack_wf_kernel<<<16, 256>>>(Wf);
    pack_x_kernel<<<dim3(M_ROWS / 64, KP / 32), 256>>>(x, Xh, Xl);

    // fused QKV: 3 weights x 8 col-blocks
    bf16x2_gemm_kernel<true><<<dim3(24, M_ROWS / 128), 256, GEMM_SMEM_BYTES>>>(
        Xh, Xl, Wh, Wl, q, k, v, M_ROWS, DM);

    featmap_mma_kernel<<<dim3(FROWS / 128, 2), 256, FEAT_SMEM_BYTES>>>();

    chunk_sums_mma_kernel<<<dim3(NCH, BHn), 256, CS_SMEM_BYTES>>>();
    prefix_kernel<<<2080, 256>>>();
    // chunk_out writes packed y straight into Xh/Xl (QKV GEMM is done with them)
    chunk_out_mma_kernel<<<dim3(NCH, BHn), 256, CO_SMEM_BYTES>>>();

    bf16x2_gemm_kernel<false><<<dim3(8, M_ROWS / 128), 256, GEMM_SMEM_BYTES>>>(
        Xh, Xl, Wh + 3 * WSTRIDE, Wl + 3 * WSTRIDE, out, out, out, M_ROWS, DM);
}